// round 13
// baseline (speedup 1.0000x reference)
#include <cuda_runtime.h>
#include <cuda_bf16.h>
#include <cuda_fp16.h>
#include <math.h>
#include <stdint.h>

#define BATCH 8
#define CH    512
#define NSP   4096
#define SCALE 0.044194173824159216f   // 1/sqrt(512)

#define ROWK_B 18432u   // 128 rows x 64 halves, stride 144B
#define KROW_B 17408u   // 64 rows x 128 halves, stride 272B
#define NST 4

// ---------------- scratch (device globals) ----------------
__device__ __nv_bfloat16 g_hb   [(size_t)BATCH * CH * NSP];       //  [b][c][n]
__device__ __nv_bfloat16 g_qkvb [(size_t)BATCH * 3 * CH * NSP];   //  [b][o][n]
__device__ __half        g_attn [(size_t)BATCH * NSP * NSP];      //  logits fp16
__device__ __nv_bfloat16 g_pb   [(size_t)BATCH * NSP * NSP];      //  softmax bf16
__device__ __nv_bfloat16 g_out2b[(size_t)BATCH * CH * NSP];       //  [b][c][n]
__device__ __nv_bfloat16 g_wqkvb[(size_t)3 * CH * CH];
__device__ __nv_bfloat16 g_woutb[(size_t)CH * CH];

// ---------------- helpers ----------------
__device__ __forceinline__ uint32_t pack_bf16(float x, float y) {
    __nv_bfloat162 h = __floats2bfloat162_rn(x, y);
    return *reinterpret_cast<uint32_t*>(&h);
}
__device__ __forceinline__ uint32_t pack_f16(float x, float y) {
    __half2 h = __floats2half2_rn(x, y);
    return *reinterpret_cast<uint32_t*>(&h);
}
__device__ __forceinline__ void cp16(uint32_t s, const void* g) {
    asm volatile("cp.async.cg.shared.global [%0], [%1], 16;\n" :: "r"(s), "l"(g));
}
__device__ __forceinline__ void mbar_init(uint32_t a, uint32_t cnt) {
    asm volatile("mbarrier.init.shared.b64 [%0], %1;" :: "r"(a), "r"(cnt) : "memory");
}
__device__ __forceinline__ void mbar_wait(uint32_t a, uint32_t par) {
    uint32_t done;
    asm volatile("{\n\t.reg .pred p;\n\t"
        "mbarrier.try_wait.parity.acquire.cta.shared::cta.b64 p, [%1], %2;\n\t"
        "selp.b32 %0, 1, 0, p;\n\t}" : "=r"(done) : "r"(a), "r"(par) : "memory");
    while (!done) {
        asm volatile("{\n\t.reg .pred p;\n\t"
            "mbarrier.try_wait.parity.acquire.cta.shared::cta.b64 p, [%1], %2, 0x989680;\n\t"
            "selp.b32 %0, 1, 0, p;\n\t}" : "=r"(done) : "r"(a), "r"(par) : "memory");
    }
}
__device__ __forceinline__ void mma_bf16(float* d, const uint32_t* a, const uint32_t* b) {
    asm volatile(
        "mma.sync.aligned.m16n8k16.row.col.f32.bf16.bf16.f32 "
        "{%0,%1,%2,%3}, {%4,%5,%6,%7}, {%8,%9}, {%0,%1,%2,%3};\n"
        : "+f"(d[0]), "+f"(d[1]), "+f"(d[2]), "+f"(d[3])
        : "r"(a[0]), "r"(a[1]), "r"(a[2]), "r"(a[3]), "r"(b[0]), "r"(b[1]));
}
__device__ __forceinline__ void ldm_x4(uint32_t* r, uint32_t addr) {
    asm volatile("ldmatrix.sync.aligned.m8n8.x4.shared.b16 {%0,%1,%2,%3}, [%4];\n"
                 : "=r"(r[0]), "=r"(r[1]), "=r"(r[2]), "=r"(r[3]) : "r"(addr));
}
__device__ __forceinline__ void ldm_x4t(uint32_t* r, uint32_t addr) {
    asm volatile("ldmatrix.sync.aligned.m8n8.x4.trans.shared.b16 {%0,%1,%2,%3}, [%4];\n"
                 : "=r"(r[0]), "=r"(r[1]), "=r"(r[2]), "=r"(r[3]) : "r"(addr));
}

// ---------------- producer staging (128 threads) ----------------
__device__ __forceinline__ void pstage_rowk(uint32_t sb, const __nv_bfloat16* g,
                                            size_t ld, int pt) {
#pragma unroll
    for (int p = 0; p < 8; p++) {
        const int idx = pt + p * 128;
        const int row = idx >> 3, c = idx & 7;
        cp16(sb + row * 144 + c * 16, g + (size_t)row * ld + c * 8);
    }
}
__device__ __forceinline__ void pstage_krow(uint32_t sb, const __nv_bfloat16* g,
                                            size_t ld, int pt) {
#pragma unroll
    for (int p = 0; p < 8; p++) {
        const int idx = pt + p * 128;
        const int row = idx >> 4, c = idx & 15;
        cp16(sb + row * 272 + c * 16, g + (size_t)row * ld + c * 8);
    }
}

// ---------------- ldmatrix fragment loaders (R6-proven) ----------------
__device__ __forceinline__ void ldA_rowk(uint32_t* a, uint32_t base, int M0, int kk) {
    const int l = threadIdx.x & 31;
    const uint32_t addr = base + (uint32_t)(M0 + (l & 15)) * 144
                               + (uint32_t)(kk + ((l >> 4) << 3)) * 2;
    ldm_x4(a, addr);
}
__device__ __forceinline__ void ldB_rowk(uint32_t* b, uint32_t base, int N0, int kk) {
    const int l = threadIdx.x & 31;
    const uint32_t addr = base + (uint32_t)(N0 + ((l >> 4) << 3) + (l & 7)) * 144
                               + (uint32_t)(kk + (((l >> 3) & 1) << 3)) * 2;
    ldm_x4(b, addr);
}
__device__ __forceinline__ void ldA_krow(uint32_t* a, uint32_t base, int M0, int kk) {
    const int l = threadIdx.x & 31;
    const int gq = l >> 3, lr = l & 7;
    const uint32_t addr = base + (uint32_t)(kk + lr + ((gq & 2) ? 8 : 0)) * 272
                               + (uint32_t)(M0 + ((gq & 1) ? 8 : 0)) * 2;
    ldm_x4t(a, addr);
}
__device__ __forceinline__ void ldB_krow(uint32_t* b, uint32_t base, int N0, int kk) {
    const int l = threadIdx.x & 31;
    const int gq = l >> 3, lr = l & 7;
    const uint32_t addr = base + (uint32_t)(kk + lr + ((gq & 1) ? 8 : 0)) * 272
                               + (uint32_t)(N0 + ((gq & 2) ? 8 : 0)) * 2;
    ldm_x4t(b, addr);
}

// ---------------- one k16-step fragment load ----------------
template <bool AT, int BM>
__device__ __forceinline__ void loadstep(uint32_t A, uint32_t B, int ks,
                                         uint32_t a[4][4], uint32_t bb[2][4],
                                         int wm, int wn) {
#pragma unroll
    for (int i = 0; i < 4; i++) {
        if (AT) ldA_krow(a[i], A, wm * 64 + i * 16, ks * 16);
        else    ldA_rowk(a[i], A, wm * 64 + i * 16, ks * 16);
    }
    if (BM == 1) {
        ldB_krow(bb[0], B, wn * 32 + 0,  ks * 16);
        ldB_krow(bb[1], B, wn * 32 + 16, ks * 16);
    } else {
        ldB_rowk(bb[0], B, wn * 32 + 0,  ks * 16);
        ldB_rowk(bb[1], B, wn * 32 + 16, ks * 16);
    }
}

// ---------------- chunk compute (128x128x64), 64x32 tile, reg double-buffered ----------------
template <bool AT, int BM>
__device__ __forceinline__ void comp(uint32_t A, uint32_t B,
                                     float acc[4][4][4], int wm, int wn) {
    uint32_t a[2][4][4], bb[2][2][4];
    loadstep<AT, BM>(A, B, 0, a[0], bb[0], wm, wn);
#pragma unroll
    for (int ks = 0; ks < 4; ks++) {
        const int cur = ks & 1, nxt = cur ^ 1;
        if (ks < 3) loadstep<AT, BM>(A, B, ks + 1, a[nxt], bb[nxt], wm, wn);
#pragma unroll
        for (int i = 0; i < 4; i++)
#pragma unroll
            for (int j = 0; j < 4; j++)
                mma_bf16(acc[i][j], a[cur][i], &bb[cur][j >> 1][(j & 1) * 2]);
    }
}

// ---------------- warp-specialized GEMM core ----------------
template <bool AT, int BM>
__device__ __forceinline__ void gemm_ws(uint32_t sbase,
                                        const __nv_bfloat16* Ag, size_t lda,
                                        const __nv_bfloat16* Bg, size_t ldb,
                                        int NC, float acc[4][4][4]) {
    constexpr uint32_t ASZ = AT ? KROW_B : ROWK_B;
    constexpr uint32_t BSZ = (BM == 1) ? KROW_B : ROWK_B;
    const uint32_t sA0 = sbase + 128, sB0 = sA0 + NST * ASZ;
    const int tid = threadIdx.x, wid = tid >> 5, lane = tid & 31;

    if (tid == 0) {
#pragma unroll
        for (int s = 0; s < NST; s++) {
            mbar_init(sbase + 8 * s, 128);       // full: 128 producer threads (noinc)
            mbar_init(sbase + 64 + 8 * s, 8);    // empty: 8 consumer warps
        }
    }
    __syncthreads();

    if (wid >= 8) {
        const int pt = tid & 127;
        int s = 0, ph = 1;
        for (int c = 0; c < NC; c++) {
            mbar_wait(sbase + 64 + 8 * s, ph);
            const __nv_bfloat16* ga = Ag + (AT ? (size_t)(c * 64) * lda : (size_t)(c * 64));
            const __nv_bfloat16* gb = Bg + ((BM == 1) ? (size_t)(c * 64) * ldb : (size_t)(c * 64));
            if (AT) pstage_krow(sA0 + s * ASZ, ga, lda, pt);
            else    pstage_rowk(sA0 + s * ASZ, ga, lda, pt);
            if (BM == 1) pstage_krow(sB0 + s * BSZ, gb, ldb, pt);
            else         pstage_rowk(sB0 + s * BSZ, gb, ldb, pt);
            asm volatile("cp.async.mbarrier.arrive.noinc.shared.b64 [%0];"
                         :: "r"(sbase + 8 * s) : "memory");
            if (++s == NST) { s = 0; ph ^= 1; }
        }
    } else {
        const int wm = wid >> 2, wn = wid & 3;
        int s = 0, ph = 0;
        for (int c = 0; c < NC; c++) {
            mbar_wait(sbase + 8 * s, ph);
            comp<AT, BM>(sA0 + s * ASZ, sB0 + s * BSZ, acc, wm, wn);
            __syncwarp();
            if (lane == 0)
                asm volatile("mbarrier.arrive.shared.b64 _, [%0];"
                             :: "r"(sbase + 64 + 8 * s) : "memory");
            if (++s == NST) { s = 0; ph ^= 1; }
        }
    }
}

// ---------------- weight convert ----------------
__global__ void convert_kernel(const float* __restrict__ src,
                               __nv_bfloat16* __restrict__ dst, int n4) {
    const int i = blockIdx.x * 256 + threadIdx.x;
    if (i < n4) {
        float4 v = ((const float4*)src)[i];
        uint2 o;
        o.x = pack_bf16(v.x, v.y);
        o.y = pack_bf16(v.z, v.w);
        ((uint2*)dst)[i] = o;
    }
}

// ---------------- GroupNorm -> bf16 h [b][c][n] ----------------
__global__ void gn_kernel(const float* __restrict__ x,
                          const float* __restrict__ gamma,
                          const float* __restrict__ beta) {
    const int b = blockIdx.x >> 5;
    const int g = blockIdx.x & 31;
    const size_t base = ((size_t)b * CH + (size_t)g * 16) * NSP;
    const float4* x4 = (const float4*)(x + base);
    uint2* h4 = (uint2*)(g_hb + base);
    const int tid = threadIdx.x;
    const int NV = 16 * NSP / 4;

    float s = 0.f, ss = 0.f;
    for (int i = tid; i < NV; i += 512) {
        float4 v = x4[i];
        s  += v.x + v.y + v.z + v.w;
        ss += v.x * v.x + v.y * v.y + v.z * v.z + v.w * v.w;
    }
    __shared__ float rs[512], rq[512];
    rs[tid] = s; rq[tid] = ss;
    __syncthreads();
    for (int o = 256; o > 0; o >>= 1) {
        if (tid < o) { rs[tid] += rs[tid + o]; rq[tid] += rq[tid + o]; }
        __syncthreads();
    }
    const float inv_n = 1.f / (float)(16 * NSP);
    const float mean  = rs[0] * inv_n;
    const float var   = rq[0] * inv_n - mean * mean;
    const float rstd  = rsqrtf(var + 1e-5f);

    for (int i = tid; i < NV; i += 512) {
        const int c = g * 16 + (i >> 10);
        const float ga = gamma[c] * rstd;
        const float be = beta[c] - mean * ga;
        float4 v = x4[i];
        uint2 o;
        o.x = pack_bf16(v.x * ga + be, v.y * ga + be);
        o.y = pack_bf16(v.z * ga + be, v.w * ga + be);
        h4[i] = o;
    }
}

// ---------------- QKV ----------------
__global__ __launch_bounds__(384, 1) void qkv_kernel(const float* __restrict__ bias) {
    const int b = blockIdx.z;
    const int m0 = blockIdx.y * 128, n0 = blockIdx.x * 128;
    extern __shared__ __align__(16) char smem[];
    const uint32_t sbase = (uint32_t)__cvta_generic_to_shared(smem);
    float acc[4][4][4] = {};
    gemm_ws<false, 1>(sbase, g_wqkvb + (size_t)m0 * CH, CH,
                      g_hb + (size_t)b * CH * NSP + n0, NSP, 8, acc);
    const int wid = threadIdx.x >> 5;
    if (wid >= 8) return;
    const int lane = threadIdx.x & 31, wm = wid >> 2, wn = wid & 3;
    const float mult = (blockIdx.y < 4) ? SCALE : 1.0f;
    __nv_bfloat16* out = g_qkvb + (size_t)b * 3 * CH * NSP;
#pragma unroll
    for (int i = 0; i < 4; i++) {
        const int m = m0 + wm * 64 + i * 16 + (lane >> 2);
        const float b0 = bias[m], b1 = bias[m + 8];
#pragma unroll
        for (int j = 0; j < 4; j++) {
            const int n = n0 + wn * 32 + j * 8 + 2 * (lane & 3);
            *(uint32_t*)(out + (size_t)m * NSP + n) =
                pack_bf16((acc[i][j][0] + b0) * mult, (acc[i][j][1] + b0) * mult);
            *(uint32_t*)(out + (size_t)(m + 8) * NSP + n) =
                pack_bf16((acc[i][j][2] + b1) * mult, (acc[i][j][3] + b1) * mult);
        }
    }
}

// ---------------- S = q^T k (scale pre-folded), fp16 out ----------------
__global__ __launch_bounds__(384, 1) void s_kernel() {
    const int b = blockIdx.z;
    const int i0 = blockIdx.y * 128, j0 = blockIdx.x * 128;
    extern __shared__ __align__(16) char smem[];
    const uint32_t sbase = (uint32_t)__cvta_generic_to_shared(smem);
    float acc[4][4][4] = {};
    gemm_ws<true, 1>(sbase, g_qkvb + (size_t)b * 3 * CH * NSP + i0, NSP,
                     g_qkvb + ((size_t)b * 3 + 1) * CH * NSP + j0, NSP, 8, acc);
    const int wid = threadIdx.x >> 5;
    if (wid >= 8) return;
    const int lane = threadIdx.x & 31, wm = wid >> 2, wn = wid & 3;
    __half* Sp = g_attn + (size_t)b * NSP * NSP;
#pragma unroll
    for (int i = 0; i < 4; i++) {
        const int m = i0 + wm * 64 + i * 16 + (lane >> 2);
#pragma unroll
        for (int j = 0; j < 4; j++) {
            const int n = j0 + wn * 32 + j * 8 + 2 * (lane & 3);
            *(uint32_t*)(Sp + (size_t)m * NSP + n) = pack_f16(acc[i][j][0], acc[i][j][1]);
            *(uint32_t*)(Sp + (size_t)(m + 8) * NSP + n) = pack_f16(acc[i][j][2], acc[i][j][3]);
        }
    }
}

// ---------------- softmax: read fp16 S, write bf16 P ----------------
__global__ void softmax_kernel() {
    const size_t row = (size_t)blockIdx.y * NSP + blockIdx.x;
    const uint4* p = (const uint4*)(g_attn + row * NSP);
    uint4* pb = (uint4*)(g_pb + row * NSP);
    const int tid = threadIdx.x;
    const int lane = tid & 31, wid = tid >> 5;

    uint4 raw[2];
    float v[16];
    float mx = -1e30f;
#pragma unroll
    for (int u = 0; u < 2; u++) {
        raw[u] = p[tid + u * 256];
        const uint32_t* w = (const uint32_t*)&raw[u];
#pragma unroll
        for (int q = 0; q < 4; q++) {
            float2 f = __half22float2(*(const __half2*)&w[q]);
            v[u * 8 + q * 2] = f.x; v[u * 8 + q * 2 + 1] = f.y;
            mx = fmaxf(mx, fmaxf(f.x, f.y));
        }
    }
#pragma unroll
    for (int o = 16; o > 0; o >>= 1) mx = fmaxf(mx, __shfl_xor_sync(~0u, mx, o));
    __shared__ float red[8];
    if (lane == 0) red[wid] = mx;
    __syncthreads();
    mx = fmaxf(fmaxf(fmaxf(red[0], red[1]), fmaxf(red[2], red[3])),
               fmaxf(fmaxf(red[4], red[5]), fmaxf(red[6], red[7])));

    float s = 0.f;
#pragma unroll
    for (int u = 0; u < 16; u++) { v[u] = __expf(v[u] - mx); s += v[u]; }
#pragma unroll
    for (int o = 16; o > 0; o >>= 1) s += __shfl_xor_sync(~0u, s, o);
    __shared__ float red2[8];
    if (lane == 0) red2[wid] = s;
    __syncthreads();
    s = (red2[0] + red2[1]) + (red2[2] + red2[3]) + (red2[4] + red2[5]) + (red2[6] + red2[7]);
    const float inv = 1.f / s;
#pragma unroll
    for (int u = 0; u < 2; u++) {
        uint4 o;
        uint32_t* w = (uint32_t*)&o;
#pragma unroll
        for (int q = 0; q < 4; q++)
            w[q] = pack_bf16(v[u * 8 + q * 2] * inv, v[u * 8 + q * 2 + 1] * inv);
        pb[tid + u * 256] = o;
    }
}

// ---------------- AV: out2[c,i] = sum_j V[c,j] * P[i,j] ----------------
__global__ __launch_bounds__(384, 1) void av_kernel() {
    const int b = blockIdx.z;
    const int m0 = blockIdx.x * 128, n0 = blockIdx.y * 128;   // m=c, n=i
    extern __shared__ __align__(16) char smem[];
    const uint32_t sbase = (uint32_t)__cvta_generic_to_shared(smem);
    float acc[4][4][4] = {};
    gemm_ws<false, 0>(sbase,
                      g_qkvb + ((size_t)b * 3 + 2) * CH * NSP + (size_t)m0 * NSP, NSP,
                      g_pb + (size_t)b * NSP * NSP + (size_t)n0 * NSP, NSP, 64, acc);
    const int wid = threadIdx.x >> 5;
    if (wid >= 8) return;
    const int lane = threadIdx.x & 31, wm = wid >> 2, wn = wid & 3;
    __nv_bfloat16* out = g_out2b + (size_t)b * CH * NSP;
#pragma unroll
    for (int i = 0; i < 4; i++) {
        const int m = m0 + wm * 64 + i * 16 + (lane >> 2);
#pragma unroll
        for (int j = 0; j < 4; j++) {
            const int n = n0 + wn * 32 + j * 8 + 2 * (lane & 3);
            *(uint32_t*)(out + (size_t)m * NSP + n) = pack_bf16(acc[i][j][0], acc[i][j][1]);
            *(uint32_t*)(out + (size_t)(m + 8) * NSP + n) = pack_bf16(acc[i][j][2], acc[i][j][3]);
        }
    }
}

// ---------------- out: y = x + Wout @ out2 + b_out (fp32) ----------------
__global__ __launch_bounds__(384, 1) void out_kernel(const float* __restrict__ bias,
                                                     const float* __restrict__ x,
                                                     float* __restrict__ y) {
    const int b = blockIdx.z;
    const int m0 = blockIdx.y * 128, n0 = blockIdx.x * 128;
    extern __shared__ __align__(16) char smem[];
    const uint32_t sbase = (uint32_t)__cvta_generic_to_shared(smem);
    float acc[4][4][4] = {};
    gemm_ws<false, 1>(sbase, g_woutb + (size_t)m0 * CH, CH,
                      g_out2b + (size_t)b * CH * NSP + n0, NSP, 8, acc);
    const int wid = threadIdx.x >> 5;
    if (wid >= 8) return;
    const int lane = threadIdx.x & 31, wm = wid >> 2, wn = wid & 3;
#pragma unroll
    for (int i = 0; i < 4; i++) {
        const int m = m0 + wm * 64 + i * 16 + (lane >> 2);
        const float b0 = bias[m], b1 = bias[m + 8];
#pragma unroll
        for (int j = 0; j < 4; j++) {
            const int n = n0 + wn * 32 + j * 8 + 2 * (lane & 3);
            const size_t o0 = ((size_t)b * CH + m) * NSP + n;
            const size_t o1 = ((size_t)b * CH + m + 8) * NSP + n;
            float2 x0 = *(const float2*)(x + o0);
            float2 x1 = *(const float2*)(x + o1);
            *(float2*)(y + o0) =
                make_float2(acc[i][j][0] + b0 + x0.x, acc[i][j][1] + b0 + x0.y);
            *(float2*)(y + o1) =
                make_float2(acc[i][j][2] + b1 + x1.x, acc[i][j][3] + b1 + x1.y);
        }
    }
}

// ---------------- launch ----------------
extern "C" void kernel_launch(void* const* d_in, const int* in_sizes, int n_in,
                              void* d_out, int out_size) {
    const float* x     = (const float*)d_in[0];
    const float* gamma = (const float*)d_in[1];
    const float* beta  = (const float*)d_in[2];
    const float* w_qkv = (const float*)d_in[3];
    const float* b_qkv = (const float*)d_in[4];
    const float* w_out = (const float*)d_in[5];
    const float* b_out = (const float*)d_in[6];
    float* y = (float*)d_out;

    __nv_bfloat16* wq; cudaGetSymbolAddress((void**)&wq, g_wqkvb);
    __nv_bfloat16* wo; cudaGetSymbolAddress((void**)&wo, g_woutb);

    const int SM_MIX = 128 + NST * (ROWK_B + KROW_B);  // 143488
    const int SM_KK  = 128 + NST * (2 * KROW_B);       // 139392
    const int SM_RR  = 128 + NST * (2 * ROWK_B);       // 147584
    cudaFuncSetAttribute(qkv_kernel, cudaFuncAttributeMaxDynamicSharedMemorySize, SM_MIX);
    cudaFuncSetAttribute(s_kernel,   cudaFuncAttributeMaxDynamicSharedMemorySize, SM_KK);
    cudaFuncSetAttribute(av_kernel,  cudaFuncAttributeMaxDynamicSharedMemorySize, SM_RR);
    cudaFuncSetAttribute(out_kernel, cudaFuncAttributeMaxDynamicSharedMemorySize, SM_MIX);

    convert_kernel<<<768, 256>>>(w_qkv, wq, 3 * CH * CH / 4);
    convert_kernel<<<256, 256>>>(w_out, wo, CH * CH / 4);
    gn_kernel<<<BATCH * 32, 512>>>(x, gamma, beta);
    qkv_kernel<<<dim3(NSP / 128, 3 * CH / 128, BATCH), 384, SM_MIX>>>(b_qkv);
    s_kernel<<<dim3(NSP / 128, NSP / 128, BATCH), 384, SM_KK>>>();
    softmax_kernel<<<dim3(NSP, BATCH), 256>>>();
    av_kernel<<<dim3(CH / 128, NSP / 128, BATCH), 384, SM_RR>>>();
    out_kernel<<<dim3(NSP / 128, CH / 128, BATCH), 384, SM_MIX>>>(b_out, x, y);
}

// round 14
// speedup vs baseline: 1.0255x; 1.0255x over previous
#include <cuda_runtime.h>
#include <cuda_bf16.h>
#include <cuda_fp16.h>
#include <math.h>
#include <stdint.h>

#define BATCH 8
#define CH    512
#define NSP   4096
#define SCALE 0.044194173824159216f   // 1/sqrt(512)

#define ROWK_B 18432u   // 128 rows x 64 halves, stride 144B
#define KROW_B 17408u   // 64 rows x 128 halves, stride 272B
#define NST 4

// ---------------- scratch (device globals) ----------------
__device__ __nv_bfloat16 g_hb   [(size_t)BATCH * CH * NSP];       //  [b][c][n]
__device__ __nv_bfloat16 g_qkvb [(size_t)BATCH * 3 * CH * NSP];   //  [b][o][n]
__device__ __half        g_attn [(size_t)BATCH * NSP * NSP];      //  logits fp16
__device__ __nv_bfloat16 g_pb   [(size_t)BATCH * NSP * NSP];      //  softmax bf16
__device__ __nv_bfloat16 g_out2b[(size_t)BATCH * CH * NSP];       //  [b][c][n]
__device__ __nv_bfloat16 g_wqkvb[(size_t)3 * CH * CH];
__device__ __nv_bfloat16 g_woutb[(size_t)CH * CH];

// ---------------- helpers ----------------
__device__ __forceinline__ uint32_t pack_bf16(float x, float y) {
    __nv_bfloat162 h = __floats2bfloat162_rn(x, y);
    return *reinterpret_cast<uint32_t*>(&h);
}
__device__ __forceinline__ uint32_t pack_f16(float x, float y) {
    __half2 h = __floats2half2_rn(x, y);
    return *reinterpret_cast<uint32_t*>(&h);
}
__device__ __forceinline__ void cp16(uint32_t s, const void* g) {
    asm volatile("cp.async.cg.shared.global [%0], [%1], 16;\n" :: "r"(s), "l"(g));
}
__device__ __forceinline__ void mbar_init(uint32_t a, uint32_t cnt) {
    asm volatile("mbarrier.init.shared.b64 [%0], %1;" :: "r"(a), "r"(cnt) : "memory");
}
__device__ __forceinline__ void mbar_wait(uint32_t a, uint32_t par) {
    uint32_t done;
    asm volatile("{\n\t.reg .pred p;\n\t"
        "mbarrier.try_wait.parity.acquire.cta.shared::cta.b64 p, [%1], %2;\n\t"
        "selp.b32 %0, 1, 0, p;\n\t}" : "=r"(done) : "r"(a), "r"(par) : "memory");
    while (!done) {
        asm volatile("{\n\t.reg .pred p;\n\t"
            "mbarrier.try_wait.parity.acquire.cta.shared::cta.b64 p, [%1], %2, 0x989680;\n\t"
            "selp.b32 %0, 1, 0, p;\n\t}" : "=r"(done) : "r"(a), "r"(par) : "memory");
    }
}
__device__ __forceinline__ void mma_bf16(float* d, const uint32_t* a, const uint32_t* b) {
    asm volatile(
        "mma.sync.aligned.m16n8k16.row.col.f32.bf16.bf16.f32 "
        "{%0,%1,%2,%3}, {%4,%5,%6,%7}, {%8,%9}, {%0,%1,%2,%3};\n"
        : "+f"(d[0]), "+f"(d[1]), "+f"(d[2]), "+f"(d[3])
        : "r"(a[0]), "r"(a[1]), "r"(a[2]), "r"(a[3]), "r"(b[0]), "r"(b[1]));
}
__device__ __forceinline__ void ldm_x4(uint32_t* r, uint32_t addr) {
    asm volatile("ldmatrix.sync.aligned.m8n8.x4.shared.b16 {%0,%1,%2,%3}, [%4];\n"
                 : "=r"(r[0]), "=r"(r[1]), "=r"(r[2]), "=r"(r[3]) : "r"(addr));
}
__device__ __forceinline__ void ldm_x4t(uint32_t* r, uint32_t addr) {
    asm volatile("ldmatrix.sync.aligned.m8n8.x4.trans.shared.b16 {%0,%1,%2,%3}, [%4];\n"
                 : "=r"(r[0]), "=r"(r[1]), "=r"(r[2]), "=r"(r[3]) : "r"(addr));
}

// ---------------- producer staging (128 threads) ----------------
__device__ __forceinline__ void pstage_rowk(uint32_t sb, const __nv_bfloat16* g,
                                            size_t ld, int pt) {
#pragma unroll
    for (int p = 0; p < 8; p++) {
        const int idx = pt + p * 128;
        const int row = idx >> 3, c = idx & 7;
        cp16(sb + row * 144 + c * 16, g + (size_t)row * ld + c * 8);
    }
}
__device__ __forceinline__ void pstage_krow(uint32_t sb, const __nv_bfloat16* g,
                                            size_t ld, int pt) {
#pragma unroll
    for (int p = 0; p < 8; p++) {
        const int idx = pt + p * 128;
        const int row = idx >> 4, c = idx & 15;
        cp16(sb + row * 272 + c * 16, g + (size_t)row * ld + c * 8);
    }
}

// ---------------- ldmatrix fragment loaders (R6-proven) ----------------
__device__ __forceinline__ void ldA_rowk(uint32_t* a, uint32_t base, int M0, int kk) {
    const int l = threadIdx.x & 31;
    const uint32_t addr = base + (uint32_t)(M0 + (l & 15)) * 144
                               + (uint32_t)(kk + ((l >> 4) << 3)) * 2;
    ldm_x4(a, addr);
}
__device__ __forceinline__ void ldB_rowk(uint32_t* b, uint32_t base, int N0, int kk) {
    const int l = threadIdx.x & 31;
    const uint32_t addr = base + (uint32_t)(N0 + ((l >> 4) << 3) + (l & 7)) * 144
                               + (uint32_t)(kk + (((l >> 3) & 1) << 3)) * 2;
    ldm_x4(b, addr);
}
__device__ __forceinline__ void ldA_krow(uint32_t* a, uint32_t base, int M0, int kk) {
    const int l = threadIdx.x & 31;
    const int gq = l >> 3, lr = l & 7;
    const uint32_t addr = base + (uint32_t)(kk + lr + ((gq & 2) ? 8 : 0)) * 272
                               + (uint32_t)(M0 + ((gq & 1) ? 8 : 0)) * 2;
    ldm_x4t(a, addr);
}
__device__ __forceinline__ void ldB_krow(uint32_t* b, uint32_t base, int N0, int kk) {
    const int l = threadIdx.x & 31;
    const int gq = l >> 3, lr = l & 7;
    const uint32_t addr = base + (uint32_t)(kk + lr + ((gq & 1) ? 8 : 0)) * 272
                               + (uint32_t)(N0 + ((gq & 2) ? 8 : 0)) * 2;
    ldm_x4t(b, addr);
}

// ---------------- one k16-step fragment load ----------------
template <bool AT, int BM>
__device__ __forceinline__ void loadstep(uint32_t A, uint32_t B, int ks,
                                         uint32_t a[4][4], uint32_t bb[2][4],
                                         int wm, int wn) {
#pragma unroll
    for (int i = 0; i < 4; i++) {
        if (AT) ldA_krow(a[i], A, wm * 64 + i * 16, ks * 16);
        else    ldA_rowk(a[i], A, wm * 64 + i * 16, ks * 16);
    }
    if (BM == 1) {
        ldB_krow(bb[0], B, wn * 32 + 0,  ks * 16);
        ldB_krow(bb[1], B, wn * 32 + 16, ks * 16);
    } else {
        ldB_rowk(bb[0], B, wn * 32 + 0,  ks * 16);
        ldB_rowk(bb[1], B, wn * 32 + 16, ks * 16);
    }
}

// ---------------- chunk compute (128x128x64), 64x32 tile, reg double-buffered ----------------
template <bool AT, int BM>
__device__ __forceinline__ void comp(uint32_t A, uint32_t B,
                                     float acc[4][4][4], int wm, int wn) {
    uint32_t a[2][4][4], bb[2][2][4];
    loadstep<AT, BM>(A, B, 0, a[0], bb[0], wm, wn);
#pragma unroll
    for (int ks = 0; ks < 4; ks++) {
        const int cur = ks & 1, nxt = cur ^ 1;
        if (ks < 3) loadstep<AT, BM>(A, B, ks + 1, a[nxt], bb[nxt], wm, wn);
#pragma unroll
        for (int i = 0; i < 4; i++)
#pragma unroll
            for (int j = 0; j < 4; j++)
                mma_bf16(acc[i][j], a[cur][i], &bb[cur][j >> 1][(j & 1) * 2]);
    }
}

// ---------------- persistent warp-specialized GEMM core (TPC tiles per CTA) ----------------
template <bool AT, int BM, class Epi>
__device__ __forceinline__ void gemm_ws_multi(uint32_t sbase,
                                              const __nv_bfloat16* Ag, size_t lda, size_t astep,
                                              const __nv_bfloat16* Bg, size_t ldb, size_t bstep,
                                              int NC, int TPC, const Epi& epi) {
    constexpr uint32_t ASZ = AT ? KROW_B : ROWK_B;
    constexpr uint32_t BSZ = (BM == 1) ? KROW_B : ROWK_B;
    const uint32_t sA0 = sbase + 128, sB0 = sA0 + NST * ASZ;
    const int tid = threadIdx.x, wid = tid >> 5, lane = tid & 31;

    if (tid == 0) {
#pragma unroll
        for (int s = 0; s < NST; s++) {
            mbar_init(sbase + 8 * s, 128);       // full: 128 producer threads (noinc)
            mbar_init(sbase + 64 + 8 * s, 8);    // empty: 8 consumer warps
        }
    }
    __syncthreads();

    if (wid >= 8) {
        // ---- producer: 4 warps, 128 threads; streams across tile boundaries ----
        const int pt = tid & 127;
        int s = 0, ph = 1;
        for (int t = 0; t < TPC; t++) {
            const __nv_bfloat16* At = Ag + (size_t)t * astep;
            const __nv_bfloat16* Bt = Bg + (size_t)t * bstep;
            for (int c = 0; c < NC; c++) {
                mbar_wait(sbase + 64 + 8 * s, ph);
                const __nv_bfloat16* ga = At + (AT ? (size_t)(c * 64) * lda : (size_t)(c * 64));
                const __nv_bfloat16* gb = Bt + ((BM == 1) ? (size_t)(c * 64) * ldb : (size_t)(c * 64));
                if (AT) pstage_krow(sA0 + s * ASZ, ga, lda, pt);
                else    pstage_rowk(sA0 + s * ASZ, ga, lda, pt);
                if (BM == 1) pstage_krow(sB0 + s * BSZ, gb, ldb, pt);
                else         pstage_rowk(sB0 + s * BSZ, gb, ldb, pt);
                asm volatile("cp.async.mbarrier.arrive.noinc.shared.b64 [%0];"
                             :: "r"(sbase + 8 * s) : "memory");
                if (++s == NST) { s = 0; ph ^= 1; }
            }
        }
    } else {
        // ---- consumer: 8 warps; per-tile epilogue overlaps producer prefetch ----
        const int wm = wid >> 2, wn = wid & 3;
        int s = 0, ph = 0;
        for (int t = 0; t < TPC; t++) {
            float acc[4][4][4] = {};
            for (int c = 0; c < NC; c++) {
                mbar_wait(sbase + 8 * s, ph);
                comp<AT, BM>(sA0 + s * ASZ, sB0 + s * BSZ, acc, wm, wn);
                __syncwarp();
                if (lane == 0)
                    asm volatile("mbarrier.arrive.shared.b64 _, [%0];"
                                 :: "r"(sbase + 64 + 8 * s) : "memory");
                if (++s == NST) { s = 0; ph ^= 1; }
            }
            epi(acc, t, wm, wn, lane);
        }
    }
}

// ---------------- epilogue functors ----------------
struct EpiQKV {
    const float* bias; __nv_bfloat16* out; int mbase, n0;
    __device__ void operator()(float acc[4][4][4], int t, int wm, int wn, int lane) const {
        const int m0 = mbase + t * 128;
        const float mult = (m0 < 512) ? SCALE : 1.0f;
#pragma unroll
        for (int i = 0; i < 4; i++) {
            const int m = m0 + wm * 64 + i * 16 + (lane >> 2);
            const float b0 = bias[m], b1 = bias[m + 8];
#pragma unroll
            for (int j = 0; j < 4; j++) {
                const int n = n0 + wn * 32 + j * 8 + 2 * (lane & 3);
                *(uint32_t*)(out + (size_t)m * NSP + n) =
                    pack_bf16((acc[i][j][0] + b0) * mult, (acc[i][j][1] + b0) * mult);
                *(uint32_t*)(out + (size_t)(m + 8) * NSP + n) =
                    pack_bf16((acc[i][j][2] + b1) * mult, (acc[i][j][3] + b1) * mult);
            }
        }
    }
};
struct EpiS {
    __half* Sp; int i0, jbase;
    __device__ void operator()(float acc[4][4][4], int t, int wm, int wn, int lane) const {
        const int n0 = jbase + t * 128;
#pragma unroll
        for (int i = 0; i < 4; i++) {
            const int m = i0 + wm * 64 + i * 16 + (lane >> 2);
#pragma unroll
            for (int j = 0; j < 4; j++) {
                const int n = n0 + wn * 32 + j * 8 + 2 * (lane & 3);
                *(uint32_t*)(Sp + (size_t)m * NSP + n) = pack_f16(acc[i][j][0], acc[i][j][1]);
                *(uint32_t*)(Sp + (size_t)(m + 8) * NSP + n) = pack_f16(acc[i][j][2], acc[i][j][3]);
            }
        }
    }
};
struct EpiAV {
    __nv_bfloat16* out; int m0, n0;
    __device__ void operator()(float acc[4][4][4], int t, int wm, int wn, int lane) const {
#pragma unroll
        for (int i = 0; i < 4; i++) {
            const int m = m0 + wm * 64 + i * 16 + (lane >> 2);
#pragma unroll
            for (int j = 0; j < 4; j++) {
                const int n = n0 + wn * 32 + j * 8 + 2 * (lane & 3);
                *(uint32_t*)(out + (size_t)m * NSP + n) = pack_bf16(acc[i][j][0], acc[i][j][1]);
                *(uint32_t*)(out + (size_t)(m + 8) * NSP + n) = pack_bf16(acc[i][j][2], acc[i][j][3]);
            }
        }
    }
};
struct EpiOut {
    const float* bias; const float* x; float* y; int m0, nbase; size_t boff;
    __device__ void operator()(float acc[4][4][4], int t, int wm, int wn, int lane) const {
        const int n0 = nbase + t * 128;
#pragma unroll
        for (int i = 0; i < 4; i++) {
            const int m = m0 + wm * 64 + i * 16 + (lane >> 2);
            const float b0 = bias[m], b1 = bias[m + 8];
#pragma unroll
            for (int j = 0; j < 4; j++) {
                const int n = n0 + wn * 32 + j * 8 + 2 * (lane & 3);
                const size_t o0 = boff + (size_t)m * NSP + n;
                const size_t o1 = boff + (size_t)(m + 8) * NSP + n;
                float2 x0 = *(const float2*)(x + o0);
                float2 x1 = *(const float2*)(x + o1);
                *(float2*)(y + o0) =
                    make_float2(acc[i][j][0] + b0 + x0.x, acc[i][j][1] + b0 + x0.y);
                *(float2*)(y + o1) =
                    make_float2(acc[i][j][2] + b1 + x1.x, acc[i][j][3] + b1 + x1.y);
            }
        }
    }
};

// ---------------- weight convert ----------------
__global__ void convert_kernel(const float* __restrict__ src,
                               __nv_bfloat16* __restrict__ dst, int n4) {
    const int i = blockIdx.x * 256 + threadIdx.x;
    if (i < n4) {
        float4 v = ((const float4*)src)[i];
        uint2 o;
        o.x = pack_bf16(v.x, v.y);
        o.y = pack_bf16(v.z, v.w);
        ((uint2*)dst)[i] = o;
    }
}

// ---------------- GroupNorm -> bf16 h [b][c][n] ----------------
__global__ void gn_kernel(const float* __restrict__ x,
                          const float* __restrict__ gamma,
                          const float* __restrict__ beta) {
    const int b = blockIdx.x >> 5;
    const int g = blockIdx.x & 31;
    const size_t base = ((size_t)b * CH + (size_t)g * 16) * NSP;
    const float4* x4 = (const float4*)(x + base);
    uint2* h4 = (uint2*)(g_hb + base);
    const int tid = threadIdx.x;
    const int NV = 16 * NSP / 4;

    float s = 0.f, ss = 0.f;
    for (int i = tid; i < NV; i += 512) {
        float4 v = x4[i];
        s  += v.x + v.y + v.z + v.w;
        ss += v.x * v.x + v.y * v.y + v.z * v.z + v.w * v.w;
    }
    __shared__ float rs[512], rq[512];
    rs[tid] = s; rq[tid] = ss;
    __syncthreads();
    for (int o = 256; o > 0; o >>= 1) {
        if (tid < o) { rs[tid] += rs[tid + o]; rq[tid] += rq[tid + o]; }
        __syncthreads();
    }
    const float inv_n = 1.f / (float)(16 * NSP);
    const float mean  = rs[0] * inv_n;
    const float var   = rq[0] * inv_n - mean * mean;
    const float rstd  = rsqrtf(var + 1e-5f);

    for (int i = tid; i < NV; i += 512) {
        const int c = g * 16 + (i >> 10);
        const float ga = gamma[c] * rstd;
        const float be = beta[c] - mean * ga;
        float4 v = x4[i];
        uint2 o;
        o.x = pack_bf16(v.x * ga + be, v.y * ga + be);
        o.y = pack_bf16(v.z * ga + be, v.w * ga + be);
        h4[i] = o;
    }
}

// ---------------- QKV: persistent over 4 m-tiles ----------------
__global__ __launch_bounds__(384, 1) void qkv_kernel(const float* __restrict__ bias) {
    const int b = blockIdx.z;
    const int mbase = blockIdx.y * 512, n0 = blockIdx.x * 128;
    extern __shared__ __align__(16) char smem[];
    const uint32_t sbase = (uint32_t)__cvta_generic_to_shared(smem);
    EpiQKV epi{bias, g_qkvb + (size_t)b * 3 * CH * NSP, mbase, n0};
    gemm_ws_multi<false, 1>(sbase,
        g_wqkvb + (size_t)mbase * CH, CH, (size_t)128 * CH,
        g_hb + (size_t)b * CH * NSP + n0, NSP, 0,
        8, 4, epi);
}

// ---------------- S: persistent over 4 j-tiles ----------------
__global__ __launch_bounds__(384, 1) void s_kernel() {
    const int b = blockIdx.z;
    const int i0 = blockIdx.y * 128, jbase = blockIdx.x * 512;
    extern __shared__ __align__(16) char smem[];
    const uint32_t sbase = (uint32_t)__cvta_generic_to_shared(smem);
    EpiS epi{g_attn + (size_t)b * NSP * NSP, i0, jbase};
    gemm_ws_multi<true, 1>(sbase,
        g_qkvb + (size_t)b * 3 * CH * NSP + i0, NSP, 0,
        g_qkvb + ((size_t)b * 3 + 1) * CH * NSP + jbase, NSP, 128,
        8, 4, epi);
}

// ---------------- softmax: read fp16 S, write bf16 P ----------------
__global__ void softmax_kernel() {
    const size_t row = (size_t)blockIdx.y * NSP + blockIdx.x;
    const uint4* p = (const uint4*)(g_attn + row * NSP);
    uint4* pb = (uint4*)(g_pb + row * NSP);
    const int tid = threadIdx.x;
    const int lane = tid & 31, wid = tid >> 5;

    uint4 raw[2];
    float v[16];
    float mx = -1e30f;
#pragma unroll
    for (int u = 0; u < 2; u++) {
        raw[u] = p[tid + u * 256];
        const uint32_t* w = (const uint32_t*)&raw[u];
#pragma unroll
        for (int q = 0; q < 4; q++) {
            float2 f = __half22float2(*(const __half2*)&w[q]);
            v[u * 8 + q * 2] = f.x; v[u * 8 + q * 2 + 1] = f.y;
            mx = fmaxf(mx, fmaxf(f.x, f.y));
        }
    }
#pragma unroll
    for (int o = 16; o > 0; o >>= 1) mx = fmaxf(mx, __shfl_xor_sync(~0u, mx, o));
    __shared__ float red[8];
    if (lane == 0) red[wid] = mx;
    __syncthreads();
    mx = fmaxf(fmaxf(fmaxf(red[0], red[1]), fmaxf(red[2], red[3])),
               fmaxf(fmaxf(red[4], red[5]), fmaxf(red[6], red[7])));

    float s = 0.f;
#pragma unroll
    for (int u = 0; u < 16; u++) { v[u] = __expf(v[u] - mx); s += v[u]; }
#pragma unroll
    for (int o = 16; o > 0; o >>= 1) s += __shfl_xor_sync(~0u, s, o);
    __shared__ float red2[8];
    if (lane == 0) red2[wid] = s;
    __syncthreads();
    s = (red2[0] + red2[1]) + (red2[2] + red2[3]) + (red2[4] + red2[5]) + (red2[6] + red2[7]);
    const float inv = 1.f / s;
#pragma unroll
    for (int u = 0; u < 2; u++) {
        uint4 o;
        uint32_t* w = (uint32_t*)&o;
#pragma unroll
        for (int q = 0; q < 4; q++)
            w[q] = pack_bf16(v[u * 8 + q * 2] * inv, v[u * 8 + q * 2 + 1] * inv);
        pb[tid + u * 256] = o;
    }
}

// ---------------- AV: out2[c,i] = sum_j V[c,j] * P[i,j] (single long tile) ----------------
__global__ __launch_bounds__(384, 1) void av_kernel() {
    const int b = blockIdx.z;
    const int m0 = blockIdx.x * 128, n0 = blockIdx.y * 128;   // m=c, n=i
    extern __shared__ __align__(16) char smem[];
    const uint32_t sbase = (uint32_t)__cvta_generic_to_shared(smem);
    EpiAV epi{g_out2b + (size_t)b * CH * NSP, m0, n0};
    gemm_ws_multi<false, 0>(sbase,
        g_qkvb + ((size_t)b * 3 + 2) * CH * NSP + (size_t)m0 * NSP, NSP, 0,
        g_pb + (size_t)b * NSP * NSP + (size_t)n0 * NSP, NSP, 0,
        64, 1, epi);
}

// ---------------- out: persistent over 4 n-tiles ----------------
__global__ __launch_bounds__(384, 1) void out_kernel(const float* __restrict__ bias,
                                                     const float* __restrict__ x,
                                                     float* __restrict__ y) {
    const int b = blockIdx.z;
    const int m0 = blockIdx.y * 128, nbase = blockIdx.x * 512;
    extern __shared__ __align__(16) char smem[];
    const uint32_t sbase = (uint32_t)__cvta_generic_to_shared(smem);
    EpiOut epi{bias, x, y, m0, nbase, (size_t)b * CH * NSP};
    gemm_ws_multi<false, 1>(sbase,
        g_woutb + (size_t)m0 * CH, CH, 0,
        g_out2b + (size_t)b * CH * NSP + nbase, NSP, 128,
        8, 4, epi);
}

// ---------------- launch ----------------
extern "C" void kernel_launch(void* const* d_in, const int* in_sizes, int n_in,
                              void* d_out, int out_size) {
    const float* x     = (const float*)d_in[0];
    const float* gamma = (const float*)d_in[1];
    const float* beta  = (const float*)d_in[2];
    const float* w_qkv = (const float*)d_in[3];
    const float* b_qkv = (const float*)d_in[4];
    const float* w_out = (const float*)d_in[5];
    const float* b_out = (const float*)d_in[6];
    float* y = (float*)d_out;

    __nv_bfloat16* wq; cudaGetSymbolAddress((void**)&wq, g_wqkvb);
    __nv_bfloat16* wo; cudaGetSymbolAddress((void**)&wo, g_woutb);

    const int SM_MIX = 128 + NST * (ROWK_B + KROW_B);  // 143488
    const int SM_KK  = 128 + NST * (2 * KROW_B);       // 139392
    const int SM_RR  = 128 + NST * (2 * ROWK_B);       // 147584
    cudaFuncSetAttribute(qkv_kernel, cudaFuncAttributeMaxDynamicSharedMemorySize, SM_MIX);
    cudaFuncSetAttribute(s_kernel,   cudaFuncAttributeMaxDynamicSharedMemorySize, SM_KK);
    cudaFuncSetAttribute(av_kernel,  cudaFuncAttributeMaxDynamicSharedMemorySize, SM_RR);
    cudaFuncSetAttribute(out_kernel, cudaFuncAttributeMaxDynamicSharedMemorySize, SM_MIX);

    convert_kernel<<<768, 256>>>(w_qkv, wq, 3 * CH * CH / 4);
    convert_kernel<<<256, 256>>>(w_out, wo, CH * CH / 4);
    gn_kernel<<<BATCH * 32, 512>>>(x, gamma, beta);
    qkv_kernel<<<dim3(NSP / 128, 3, BATCH), 384, SM_MIX>>>(b_qkv);         // 4 m-tiles/CTA
    s_kernel<<<dim3(NSP / 512, NSP / 128, BATCH), 384, SM_KK>>>();          // 4 j-tiles/CTA
    softmax_kernel<<<dim3(NSP, BATCH), 256>>>();
    av_kernel<<<dim3(CH / 128, NSP / 128, BATCH), 384, SM_RR>>>();
    out_kernel<<<dim3(NSP / 512, CH / 128, BATCH), 384, SM_MIX>>>(b_out, x, y);
}

// round 15
// speedup vs baseline: 1.0301x; 1.0045x over previous
#include <cuda_runtime.h>
#include <cuda_bf16.h>
#include <cuda_fp16.h>
#include <math.h>
#include <stdint.h>

#define BATCH 8
#define CH    512
#define NSP   4096
#define SCALE 0.044194173824159216f   // 1/sqrt(512)

#define ROWK_B 18432u   // 128 rows x 64 halves, stride 144B
#define KROW_B 17408u   // 64 rows x 128 halves, stride 272B
#define NST 5

// ---------------- scratch (device globals) ----------------
__device__ __nv_bfloat16 g_hb   [(size_t)BATCH * CH * NSP];       //  [b][c][n]
__device__ __nv_bfloat16 g_qkvb [(size_t)BATCH * 3 * CH * NSP];   //  [b][o][n]
__device__ __half        g_attn [(size_t)BATCH * NSP * NSP];      //  logits fp16
__device__ __nv_bfloat16 g_pb   [(size_t)BATCH * NSP * NSP];      //  softmax bf16
__device__ __nv_bfloat16 g_out2b[(size_t)BATCH * CH * NSP];       //  [b][c][n]
__device__ __nv_bfloat16 g_wqkvb[(size_t)3 * CH * CH];
__device__ __nv_bfloat16 g_woutb[(size_t)CH * CH];

// ---------------- helpers ----------------
__device__ __forceinline__ uint32_t pack_bf16(float x, float y) {
    __nv_bfloat162 h = __floats2bfloat162_rn(x, y);
    return *reinterpret_cast<uint32_t*>(&h);
}
__device__ __forceinline__ uint32_t pack_f16(float x, float y) {
    __half2 h = __floats2half2_rn(x, y);
    return *reinterpret_cast<uint32_t*>(&h);
}
__device__ __forceinline__ void cp16(uint32_t s, const void* g) {
    asm volatile("cp.async.cg.shared.global [%0], [%1], 16;\n" :: "r"(s), "l"(g));
}
__device__ __forceinline__ void mbar_init(uint32_t a, uint32_t cnt) {
    asm volatile("mbarrier.init.shared.b64 [%0], %1;" :: "r"(a), "r"(cnt) : "memory");
}
__device__ __forceinline__ void mbar_wait(uint32_t a, uint32_t par) {
    uint32_t done;
    asm volatile("{\n\t.reg .pred p;\n\t"
        "mbarrier.try_wait.parity.acquire.cta.shared::cta.b64 p, [%1], %2;\n\t"
        "selp.b32 %0, 1, 0, p;\n\t}" : "=r"(done) : "r"(a), "r"(par) : "memory");
    while (!done) {
        asm volatile("{\n\t.reg .pred p;\n\t"
            "mbarrier.try_wait.parity.acquire.cta.shared::cta.b64 p, [%1], %2, 0x989680;\n\t"
            "selp.b32 %0, 1, 0, p;\n\t}" : "=r"(done) : "r"(a), "r"(par) : "memory");
    }
}
__device__ __forceinline__ void mma_bf16(float* d, const uint32_t* a, const uint32_t* b) {
    asm volatile(
        "mma.sync.aligned.m16n8k16.row.col.f32.bf16.bf16.f32 "
        "{%0,%1,%2,%3}, {%4,%5,%6,%7}, {%8,%9}, {%0,%1,%2,%3};\n"
        : "+f"(d[0]), "+f"(d[1]), "+f"(d[2]), "+f"(d[3])
        : "r"(a[0]), "r"(a[1]), "r"(a[2]), "r"(a[3]), "r"(b[0]), "r"(b[1]));
}
__device__ __forceinline__ void ldm_x4(uint32_t* r, uint32_t addr) {
    asm volatile("ldmatrix.sync.aligned.m8n8.x4.shared.b16 {%0,%1,%2,%3}, [%4];\n"
                 : "=r"(r[0]), "=r"(r[1]), "=r"(r[2]), "=r"(r[3]) : "r"(addr));
}
__device__ __forceinline__ void ldm_x4t(uint32_t* r, uint32_t addr) {
    asm volatile("ldmatrix.sync.aligned.m8n8.x4.trans.shared.b16 {%0,%1,%2,%3}, [%4];\n"
                 : "=r"(r[0]), "=r"(r[1]), "=r"(r[2]), "=r"(r[3]) : "r"(addr));
}

// ---------------- producer staging (128 threads) ----------------
__device__ __forceinline__ void pstage_rowk(uint32_t sb, const __nv_bfloat16* g,
                                            size_t ld, int pt) {
#pragma unroll
    for (int p = 0; p < 8; p++) {
        const int idx = pt + p * 128;
        const int row = idx >> 3, c = idx & 7;
        cp16(sb + row * 144 + c * 16, g + (size_t)row * ld + c * 8);
    }
}
__device__ __forceinline__ void pstage_krow(uint32_t sb, const __nv_bfloat16* g,
                                            size_t ld, int pt) {
#pragma unroll
    for (int p = 0; p < 8; p++) {
        const int idx = pt + p * 128;
        const int row = idx >> 4, c = idx & 15;
        cp16(sb + row * 272 + c * 16, g + (size_t)row * ld + c * 8);
    }
}

// ---------------- ldmatrix fragment loaders (R6-proven) ----------------
__device__ __forceinline__ void ldA_rowk(uint32_t* a, uint32_t base, int M0, int kk) {
    const int l = threadIdx.x & 31;
    const uint32_t addr = base + (uint32_t)(M0 + (l & 15)) * 144
                               + (uint32_t)(kk + ((l >> 4) << 3)) * 2;
    ldm_x4(a, addr);
}
__device__ __forceinline__ void ldB_rowk(uint32_t* b, uint32_t base, int N0, int kk) {
    const int l = threadIdx.x & 31;
    const uint32_t addr = base + (uint32_t)(N0 + ((l >> 4) << 3) + (l & 7)) * 144
                               + (uint32_t)(kk + (((l >> 3) & 1) << 3)) * 2;
    ldm_x4(b, addr);
}
__device__ __forceinline__ void ldA_krow(uint32_t* a, uint32_t base, int M0, int kk) {
    const int l = threadIdx.x & 31;
    const int gq = l >> 3, lr = l & 7;
    const uint32_t addr = base + (uint32_t)(kk + lr + ((gq & 2) ? 8 : 0)) * 272
                               + (uint32_t)(M0 + ((gq & 1) ? 8 : 0)) * 2;
    ldm_x4t(a, addr);
}
__device__ __forceinline__ void ldB_krow(uint32_t* b, uint32_t base, int N0, int kk) {
    const int l = threadIdx.x & 31;
    const int gq = l >> 3, lr = l & 7;
    const uint32_t addr = base + (uint32_t)(kk + lr + ((gq & 1) ? 8 : 0)) * 272
                               + (uint32_t)(N0 + ((gq & 2) ? 8 : 0)) * 2;
    ldm_x4t(b, addr);
}

// ---------------- one k16-step fragment load ----------------
template <bool AT, int BM>
__device__ __forceinline__ void loadstep(uint32_t A, uint32_t B, int ks,
                                         uint32_t a[4][4], uint32_t bb[2][4],
                                         int wm, int wn) {
#pragma unroll
    for (int i = 0; i < 4; i++) {
        if (AT) ldA_krow(a[i], A, wm * 64 + i * 16, ks * 16);
        else    ldA_rowk(a[i], A, wm * 64 + i * 16, ks * 16);
    }
    if (BM == 1) {
        ldB_krow(bb[0], B, wn * 32 + 0,  ks * 16);
        ldB_krow(bb[1], B, wn * 32 + 16, ks * 16);
    } else {
        ldB_rowk(bb[0], B, wn * 32 + 0,  ks * 16);
        ldB_rowk(bb[1], B, wn * 32 + 16, ks * 16);
    }
}

// ---------------- chunk compute (128x128x64), 64x32 tile, reg double-buffered ----------------
template <bool AT, int BM>
__device__ __forceinline__ void comp(uint32_t A, uint32_t B,
                                     float acc[4][4][4], int wm, int wn) {
    uint32_t a[2][4][4], bb[2][2][4];
    loadstep<AT, BM>(A, B, 0, a[0], bb[0], wm, wn);
#pragma unroll
    for (int ks = 0; ks < 4; ks++) {
        const int cur = ks & 1, nxt = cur ^ 1;
        if (ks < 3) loadstep<AT, BM>(A, B, ks + 1, a[nxt], bb[nxt], wm, wn);
#pragma unroll
        for (int i = 0; i < 4; i++)
#pragma unroll
            for (int j = 0; j < 4; j++)
                mma_bf16(acc[i][j], a[cur][i], &bb[cur][j >> 1][(j & 1) * 2]);
    }
}

// ---------------- persistent warp-specialized GEMM core (TPC tiles per CTA) ----------------
template <bool AT, int BM, class Epi>
__device__ __forceinline__ void gemm_ws_multi(uint32_t sbase,
                                              const __nv_bfloat16* Ag, size_t lda, size_t astep,
                                              const __nv_bfloat16* Bg, size_t ldb, size_t bstep,
                                              int NC, int TPC, const Epi& epi) {
    constexpr uint32_t ASZ = AT ? KROW_B : ROWK_B;
    constexpr uint32_t BSZ = (BM == 1) ? KROW_B : ROWK_B;
    const uint32_t sA0 = sbase + 128, sB0 = sA0 + NST * ASZ;
    const int tid = threadIdx.x, wid = tid >> 5, lane = tid & 31;

    if (tid == 0) {
#pragma unroll
        for (int s = 0; s < NST; s++) {
            mbar_init(sbase + 8 * s, 128);       // full: 128 producer threads (noinc)
            mbar_init(sbase + 64 + 8 * s, 8);    // empty: 8 consumer warps
        }
    }
    __syncthreads();

    if (wid >= 8) {
        // ---- producer: 4 warps, 128 threads; streams across tile boundaries ----
        const int pt = tid & 127;
        int s = 0, ph = 1;
        for (int t = 0; t < TPC; t++) {
            const __nv_bfloat16* At = Ag + (size_t)t * astep;
            const __nv_bfloat16* Bt = Bg + (size_t)t * bstep;
            for (int c = 0; c < NC; c++) {
                mbar_wait(sbase + 64 + 8 * s, ph);
                const __nv_bfloat16* ga = At + (AT ? (size_t)(c * 64) * lda : (size_t)(c * 64));
                const __nv_bfloat16* gb = Bt + ((BM == 1) ? (size_t)(c * 64) * ldb : (size_t)(c * 64));
                if (AT) pstage_krow(sA0 + s * ASZ, ga, lda, pt);
                else    pstage_rowk(sA0 + s * ASZ, ga, lda, pt);
                if (BM == 1) pstage_krow(sB0 + s * BSZ, gb, ldb, pt);
                else         pstage_rowk(sB0 + s * BSZ, gb, ldb, pt);
                asm volatile("cp.async.mbarrier.arrive.noinc.shared.b64 [%0];"
                             :: "r"(sbase + 8 * s) : "memory");
                if (++s == NST) { s = 0; ph ^= 1; }
            }
        }
    } else {
        // ---- consumer: 8 warps; per-tile epilogue overlaps producer prefetch ----
        const int wm = wid >> 2, wn = wid & 3;
        int s = 0, ph = 0;
        for (int t = 0; t < TPC; t++) {
            float acc[4][4][4] = {};
            for (int c = 0; c < NC; c++) {
                mbar_wait(sbase + 8 * s, ph);
                comp<AT, BM>(sA0 + s * ASZ, sB0 + s * BSZ, acc, wm, wn);
                __syncwarp();
                if (lane == 0)
                    asm volatile("mbarrier.arrive.shared.b64 _, [%0];"
                                 :: "r"(sbase + 64 + 8 * s) : "memory");
                if (++s == NST) { s = 0; ph ^= 1; }
            }
            epi(acc, t, wm, wn, lane);
        }
    }
}

// ---------------- epilogue functors ----------------
struct EpiQKV {
    const float* bias; __nv_bfloat16* out; int mbase, n0;
    __device__ void operator()(float acc[4][4][4], int t, int wm, int wn, int lane) const {
        const int m0 = mbase + t * 128;
        const float mult = (m0 < 512) ? SCALE : 1.0f;
#pragma unroll
        for (int i = 0; i < 4; i++) {
            const int m = m0 + wm * 64 + i * 16 + (lane >> 2);
            const float b0 = bias[m], b1 = bias[m + 8];
#pragma unroll
            for (int j = 0; j < 4; j++) {
                const int n = n0 + wn * 32 + j * 8 + 2 * (lane & 3);
                *(uint32_t*)(out + (size_t)m * NSP + n) =
                    pack_bf16((acc[i][j][0] + b0) * mult, (acc[i][j][1] + b0) * mult);
                *(uint32_t*)(out + (size_t)(m + 8) * NSP + n) =
                    pack_bf16((acc[i][j][2] + b1) * mult, (acc[i][j][3] + b1) * mult);
            }
        }
    }
};
struct EpiS {
    __half* Sp; int i0, jbase;
    __device__ void operator()(float acc[4][4][4], int t, int wm, int wn, int lane) const {
        const int n0 = jbase + t * 128;
#pragma unroll
        for (int i = 0; i < 4; i++) {
            const int m = i0 + wm * 64 + i * 16 + (lane >> 2);
#pragma unroll
            for (int j = 0; j < 4; j++) {
                const int n = n0 + wn * 32 + j * 8 + 2 * (lane & 3);
                *(uint32_t*)(Sp + (size_t)m * NSP + n) = pack_f16(acc[i][j][0], acc[i][j][1]);
                *(uint32_t*)(Sp + (size_t)(m + 8) * NSP + n) = pack_f16(acc[i][j][2], acc[i][j][3]);
            }
        }
    }
};
struct EpiAV {
    __nv_bfloat16* out; int m0, n0;
    __device__ void operator()(float acc[4][4][4], int t, int wm, int wn, int lane) const {
#pragma unroll
        for (int i = 0; i < 4; i++) {
            const int m = m0 + wm * 64 + i * 16 + (lane >> 2);
#pragma unroll
            for (int j = 0; j < 4; j++) {
                const int n = n0 + wn * 32 + j * 8 + 2 * (lane & 3);
                *(uint32_t*)(out + (size_t)m * NSP + n) = pack_bf16(acc[i][j][0], acc[i][j][1]);
                *(uint32_t*)(out + (size_t)(m + 8) * NSP + n) = pack_bf16(acc[i][j][2], acc[i][j][3]);
            }
        }
    }
};
struct EpiOut {
    const float* bias; const float* x; float* y; int m0, nbase; size_t boff;
    __device__ void operator()(float acc[4][4][4], int t, int wm, int wn, int lane) const {
        const int n0 = nbase + t * 128;
#pragma unroll
        for (int i = 0; i < 4; i++) {
            const int m = m0 + wm * 64 + i * 16 + (lane >> 2);
            const float b0 = bias[m], b1 = bias[m + 8];
#pragma unroll
            for (int j = 0; j < 4; j++) {
                const int n = n0 + wn * 32 + j * 8 + 2 * (lane & 3);
                const size_t o0 = boff + (size_t)m * NSP + n;
                const size_t o1 = boff + (size_t)(m + 8) * NSP + n;
                float2 x0 = *(const float2*)(x + o0);
                float2 x1 = *(const float2*)(x + o1);
                *(float2*)(y + o0) =
                    make_float2(acc[i][j][0] + b0 + x0.x, acc[i][j][1] + b0 + x0.y);
                *(float2*)(y + o1) =
                    make_float2(acc[i][j][2] + b1 + x1.x, acc[i][j][3] + b1 + x1.y);
            }
        }
    }
};

// ---------------- weight convert ----------------
__global__ void convert_kernel(const float* __restrict__ src,
                               __nv_bfloat16* __restrict__ dst, int n4) {
    const int i = blockIdx.x * 256 + threadIdx.x;
    if (i < n4) {
        float4 v = ((const float4*)src)[i];
        uint2 o;
        o.x = pack_bf16(v.x, v.y);
        o.y = pack_bf16(v.z, v.w);
        ((uint2*)dst)[i] = o;
    }
}

// ---------------- GroupNorm -> bf16 h [b][c][n] ----------------
__global__ void gn_kernel(const float* __restrict__ x,
                          const float* __restrict__ gamma,
                          const float* __restrict__ beta) {
    const int b = blockIdx.x >> 5;
    const int g = blockIdx.x & 31;
    const size_t base = ((size_t)b * CH + (size_t)g * 16) * NSP;
    const float4* x4 = (const float4*)(x + base);
    uint2* h4 = (uint2*)(g_hb + base);
    const int tid = threadIdx.x;
    const int NV = 16 * NSP / 4;

    float s = 0.f, ss = 0.f;
    for (int i = tid; i < NV; i += 512) {
        float4 v = x4[i];
        s  += v.x + v.y + v.z + v.w;
        ss += v.x * v.x + v.y * v.y + v.z * v.z + v.w * v.w;
    }
    __shared__ float rs[512], rq[512];
    rs[tid] = s; rq[tid] = ss;
    __syncthreads();
    for (int o = 256; o > 0; o >>= 1) {
        if (tid < o) { rs[tid] += rs[tid + o]; rq[tid] += rq[tid + o]; }
        __syncthreads();
    }
    const float inv_n = 1.f / (float)(16 * NSP);
    const float mean  = rs[0] * inv_n;
    const float var   = rq[0] * inv_n - mean * mean;
    const float rstd  = rsqrtf(var + 1e-5f);

    for (int i = tid; i < NV; i += 512) {
        const int c = g * 16 + (i >> 10);
        const float ga = gamma[c] * rstd;
        const float be = beta[c] - mean * ga;
        float4 v = x4[i];
        uint2 o;
        o.x = pack_bf16(v.x * ga + be, v.y * ga + be);
        o.y = pack_bf16(v.z * ga + be, v.w * ga + be);
        h4[i] = o;
    }
}

// ---------------- QKV: persistent over 2 m-tiles ----------------
__global__ __launch_bounds__(384, 1) void qkv_kernel(const float* __restrict__ bias) {
    const int b = blockIdx.z;
    const int mbase = blockIdx.y * 256, n0 = blockIdx.x * 128;
    extern __shared__ __align__(16) char smem[];
    const uint32_t sbase = (uint32_t)__cvta_generic_to_shared(smem);
    EpiQKV epi{bias, g_qkvb + (size_t)b * 3 * CH * NSP, mbase, n0};
    gemm_ws_multi<false, 1>(sbase,
        g_wqkvb + (size_t)mbase * CH, CH, (size_t)128 * CH,
        g_hb + (size_t)b * CH * NSP + n0, NSP, 0,
        8, 2, epi);
}

// ---------------- S: persistent over 4 j-tiles ----------------
__global__ __launch_bounds__(384, 1) void s_kernel() {
    const int b = blockIdx.z;
    const int i0 = blockIdx.y * 128, jbase = blockIdx.x * 512;
    extern __shared__ __align__(16) char smem[];
    const uint32_t sbase = (uint32_t)__cvta_generic_to_shared(smem);
    EpiS epi{g_attn + (size_t)b * NSP * NSP, i0, jbase};
    gemm_ws_multi<true, 1>(sbase,
        g_qkvb + (size_t)b * 3 * CH * NSP + i0, NSP, 0,
        g_qkvb + ((size_t)b * 3 + 1) * CH * NSP + jbase, NSP, 128,
        8, 4, epi);
}

// ---------------- softmax: read fp16 S, write bf16 P ----------------
__global__ void softmax_kernel() {
    const size_t row = (size_t)blockIdx.y * NSP + blockIdx.x;
    const uint4* p = (const uint4*)(g_attn + row * NSP);
    uint4* pb = (uint4*)(g_pb + row * NSP);
    const int tid = threadIdx.x;
    const int lane = tid & 31, wid = tid >> 5;

    uint4 raw[2];
    float v[16];
    float mx = -1e30f;
#pragma unroll
    for (int u = 0; u < 2; u++) {
        raw[u] = p[tid + u * 256];
        const uint32_t* w = (const uint32_t*)&raw[u];
#pragma unroll
        for (int q = 0; q < 4; q++) {
            float2 f = __half22float2(*(const __half2*)&w[q]);
            v[u * 8 + q * 2] = f.x; v[u * 8 + q * 2 + 1] = f.y;
            mx = fmaxf(mx, fmaxf(f.x, f.y));
        }
    }
#pragma unroll
    for (int o = 16; o > 0; o >>= 1) mx = fmaxf(mx, __shfl_xor_sync(~0u, mx, o));
    __shared__ float red[8];
    if (lane == 0) red[wid] = mx;
    __syncthreads();
    mx = fmaxf(fmaxf(fmaxf(red[0], red[1]), fmaxf(red[2], red[3])),
               fmaxf(fmaxf(red[4], red[5]), fmaxf(red[6], red[7])));

    float s = 0.f;
#pragma unroll
    for (int u = 0; u < 16; u++) { v[u] = __expf(v[u] - mx); s += v[u]; }
#pragma unroll
    for (int o = 16; o > 0; o >>= 1) s += __shfl_xor_sync(~0u, s, o);
    __shared__ float red2[8];
    if (lane == 0) red2[wid] = s;
    __syncthreads();
    s = (red2[0] + red2[1]) + (red2[2] + red2[3]) + (red2[4] + red2[5]) + (red2[6] + red2[7]);
    const float inv = 1.f / s;
#pragma unroll
    for (int u = 0; u < 2; u++) {
        uint4 o;
        uint32_t* w = (uint32_t*)&o;
#pragma unroll
        for (int q = 0; q < 4; q++)
            w[q] = pack_bf16(v[u * 8 + q * 2] * inv, v[u * 8 + q * 2 + 1] * inv);
        pb[tid + u * 256] = o;
    }
}

// ---------------- AV: out2[c,i] = sum_j V[c,j] * P[i,j] (single long tile) ----------------
__global__ __launch_bounds__(384, 1) void av_kernel() {
    const int b = blockIdx.z;
    const int m0 = blockIdx.x * 128, n0 = blockIdx.y * 128;   // m=c, n=i
    extern __shared__ __align__(16) char smem[];
    const uint32_t sbase = (uint32_t)__cvta_generic_to_shared(smem);
    EpiAV epi{g_out2b + (size_t)b * CH * NSP, m0, n0};
    gemm_ws_multi<false, 0>(sbase,
        g_qkvb + ((size_t)b * 3 + 2) * CH * NSP + (size_t)m0 * NSP, NSP, 0,
        g_pb + (size_t)b * NSP * NSP + (size_t)n0 * NSP, NSP, 0,
        64, 1, epi);
}

// ---------------- out: persistent over 2 n-tiles ----------------
__global__ __launch_bounds__(384, 1) void out_kernel(const float* __restrict__ bias,
                                                     const float* __restrict__ x,
                                                     float* __restrict__ y) {
    const int b = blockIdx.z;
    const int m0 = blockIdx.y * 128, nbase = blockIdx.x * 256;
    extern __shared__ __align__(16) char smem[];
    const uint32_t sbase = (uint32_t)__cvta_generic_to_shared(smem);
    EpiOut epi{bias, x, y, m0, nbase, (size_t)b * CH * NSP};
    gemm_ws_multi<false, 1>(sbase,
        g_woutb + (size_t)m0 * CH, CH, 0,
        g_out2b + (size_t)b * CH * NSP + nbase, NSP, 128,
        8, 2, epi);
}

// ---------------- launch ----------------
extern "C" void kernel_launch(void* const* d_in, const int* in_sizes, int n_in,
                              void* d_out, int out_size) {
    const float* x     = (const float*)d_in[0];
    const float* gamma = (const float*)d_in[1];
    const float* beta  = (const float*)d_in[2];
    const float* w_qkv = (const float*)d_in[3];
    const float* b_qkv = (const float*)d_in[4];
    const float* w_out = (const float*)d_in[5];
    const float* b_out = (const float*)d_in[6];
    float* y = (float*)d_out;

    __nv_bfloat16* wq; cudaGetSymbolAddress((void**)&wq, g_wqkvb);
    __nv_bfloat16* wo; cudaGetSymbolAddress((void**)&wo, g_woutb);

    const int SM_MIX = 128 + NST * (ROWK_B + KROW_B);  // 179328
    const int SM_KK  = 128 + NST * (2 * KROW_B);       // 174208
    const int SM_RR  = 128 + NST * (2 * ROWK_B);       // 184448
    cudaFuncSetAttribute(qkv_kernel, cudaFuncAttributeMaxDynamicSharedMemorySize, SM_MIX);
    cudaFuncSetAttribute(s_kernel,   cudaFuncAttributeMaxDynamicSharedMemorySize, SM_KK);
    cudaFuncSetAttribute(av_kernel,  cudaFuncAttributeMaxDynamicSharedMemorySize, SM_RR);
    cudaFuncSetAttribute(out_kernel, cudaFuncAttributeMaxDynamicSharedMemorySize, SM_MIX);

    convert_kernel<<<768, 256>>>(w_qkv, wq, 3 * CH * CH / 4);
    convert_kernel<<<256, 256>>>(w_out, wo, CH * CH / 4);
    gn_kernel<<<BATCH * 32, 512>>>(x, gamma, beta);
    qkv_kernel<<<dim3(NSP / 128, 6, BATCH), 384, SM_MIX>>>(b_qkv);          // 2 m-tiles/CTA
    s_kernel<<<dim3(NSP / 512, NSP / 128, BATCH), 384, SM_KK>>>();          // 4 j-tiles/CTA
    softmax_kernel<<<dim3(NSP, BATCH), 256>>>();
    av_kernel<<<dim3(CH / 128, NSP / 128, BATCH), 384, SM_RR>>>();
    out_kernel<<<dim3(NSP / 256, CH / 128, BATCH), 384, SM_MIX>>>(b_out, x, y);
}

// round 16
// speedup vs baseline: 1.1031x; 1.0708x over previous
#include <cuda_runtime.h>
#include <cuda_bf16.h>
#include <cuda_fp16.h>
#include <math.h>
#include <stdint.h>

#define BATCH 8
#define CH    512
#define NSP   4096
#define SCALE 0.044194173824159216f   // 1/sqrt(512)

#define ROWK_B 18432u   // 128 rows x 64 halves, stride 144B
#define KROW_B 17408u   // 64 rows x 128 halves, stride 272B
#define NST 5
#define SM_BUF0 2176u   // 128 mbar + 2048 reduce scratch

// ---------------- scratch (device globals) ----------------
__device__ __nv_bfloat16 g_hb   [(size_t)BATCH * CH * NSP];       //  [b][c][n]
__device__ __nv_bfloat16 g_qkvb [(size_t)BATCH * 3 * CH * NSP];   //  [b][o][n]
__device__ __nv_bfloat16 g_pb   [(size_t)BATCH * NSP * NSP];      //  unnormalized exp(S), bf16
__device__ __nv_bfloat16 g_out2b[(size_t)BATCH * CH * NSP];       //  [b][c][n]
__device__ float         g_partial[(size_t)BATCH * 8 * NSP];      //  row-sum partials
__device__ float         g_rinv [(size_t)BATCH * NSP];            //  1/rowsum
__device__ __nv_bfloat16 g_wqkvb[(size_t)3 * CH * CH];
__device__ __nv_bfloat16 g_woutb[(size_t)CH * CH];

// ---------------- helpers ----------------
__device__ __forceinline__ uint32_t pack_bf16(float x, float y) {
    __nv_bfloat162 h = __floats2bfloat162_rn(x, y);
    return *reinterpret_cast<uint32_t*>(&h);
}
__device__ __forceinline__ void cp16(uint32_t s, const void* g) {
    asm volatile("cp.async.cg.shared.global [%0], [%1], 16;\n" :: "r"(s), "l"(g));
}
__device__ __forceinline__ void mbar_init(uint32_t a, uint32_t cnt) {
    asm volatile("mbarrier.init.shared.b64 [%0], %1;" :: "r"(a), "r"(cnt) : "memory");
}
__device__ __forceinline__ void mbar_wait(uint32_t a, uint32_t par) {
    uint32_t done;
    asm volatile("{\n\t.reg .pred p;\n\t"
        "mbarrier.try_wait.parity.acquire.cta.shared::cta.b64 p, [%1], %2;\n\t"
        "selp.b32 %0, 1, 0, p;\n\t}" : "=r"(done) : "r"(a), "r"(par) : "memory");
    while (!done) {
        asm volatile("{\n\t.reg .pred p;\n\t"
            "mbarrier.try_wait.parity.acquire.cta.shared::cta.b64 p, [%1], %2, 0x989680;\n\t"
            "selp.b32 %0, 1, 0, p;\n\t}" : "=r"(done) : "r"(a), "r"(par) : "memory");
    }
}
__device__ __forceinline__ void mma_bf16(float* d, const uint32_t* a, const uint32_t* b) {
    asm volatile(
        "mma.sync.aligned.m16n8k16.row.col.f32.bf16.bf16.f32 "
        "{%0,%1,%2,%3}, {%4,%5,%6,%7}, {%8,%9}, {%0,%1,%2,%3};\n"
        : "+f"(d[0]), "+f"(d[1]), "+f"(d[2]), "+f"(d[3])
        : "r"(a[0]), "r"(a[1]), "r"(a[2]), "r"(a[3]), "r"(b[0]), "r"(b[1]));
}
__device__ __forceinline__ void ldm_x4(uint32_t* r, uint32_t addr) {
    asm volatile("ldmatrix.sync.aligned.m8n8.x4.shared.b16 {%0,%1,%2,%3}, [%4];\n"
                 : "=r"(r[0]), "=r"(r[1]), "=r"(r[2]), "=r"(r[3]) : "r"(addr));
}
__device__ __forceinline__ void ldm_x4t(uint32_t* r, uint32_t addr) {
    asm volatile("ldmatrix.sync.aligned.m8n8.x4.trans.shared.b16 {%0,%1,%2,%3}, [%4];\n"
                 : "=r"(r[0]), "=r"(r[1]), "=r"(r[2]), "=r"(r[3]) : "r"(addr));
}

// ---------------- producer staging (128 threads) ----------------
__device__ __forceinline__ void pstage_rowk(uint32_t sb, const __nv_bfloat16* g,
                                            size_t ld, int pt) {
#pragma unroll
    for (int p = 0; p < 8; p++) {
        const int idx = pt + p * 128;
        const int row = idx >> 3, c = idx & 7;
        cp16(sb + row * 144 + c * 16, g + (size_t)row * ld + c * 8);
    }
}
__device__ __forceinline__ void pstage_krow(uint32_t sb, const __nv_bfloat16* g,
                                            size_t ld, int pt) {
#pragma unroll
    for (int p = 0; p < 8; p++) {
        const int idx = pt + p * 128;
        const int row = idx >> 4, c = idx & 15;
        cp16(sb + row * 272 + c * 16, g + (size_t)row * ld + c * 8);
    }
}

// ---------------- ldmatrix fragment loaders ----------------
__device__ __forceinline__ void ldA_rowk(uint32_t* a, uint32_t base, int M0, int kk) {
    const int l = threadIdx.x & 31;
    const uint32_t addr = base + (uint32_t)(M0 + (l & 15)) * 144
                               + (uint32_t)(kk + ((l >> 4) << 3)) * 2;
    ldm_x4(a, addr);
}
__device__ __forceinline__ void ldB_rowk(uint32_t* b, uint32_t base, int N0, int kk) {
    const int l = threadIdx.x & 31;
    const uint32_t addr = base + (uint32_t)(N0 + ((l >> 4) << 3) + (l & 7)) * 144
                               + (uint32_t)(kk + (((l >> 3) & 1) << 3)) * 2;
    ldm_x4(b, addr);
}
__device__ __forceinline__ void ldA_krow(uint32_t* a, uint32_t base, int M0, int kk) {
    const int l = threadIdx.x & 31;
    const int gq = l >> 3, lr = l & 7;
    const uint32_t addr = base + (uint32_t)(kk + lr + ((gq & 2) ? 8 : 0)) * 272
                               + (uint32_t)(M0 + ((gq & 1) ? 8 : 0)) * 2;
    ldm_x4t(a, addr);
}
__device__ __forceinline__ void ldB_krow(uint32_t* b, uint32_t base, int N0, int kk) {
    const int l = threadIdx.x & 31;
    const int gq = l >> 3, lr = l & 7;
    const uint32_t addr = base + (uint32_t)(kk + lr + ((gq & 1) ? 8 : 0)) * 272
                               + (uint32_t)(N0 + ((gq & 2) ? 8 : 0)) * 2;
    ldm_x4t(b, addr);
}

// ---------------- one k16-step fragment load ----------------
template <bool AT, int BM>
__device__ __forceinline__ void loadstep(uint32_t A, uint32_t B, int ks,
                                         uint32_t a[4][4], uint32_t bb[2][4],
                                         int wm, int wn) {
#pragma unroll
    for (int i = 0; i < 4; i++) {
        if (AT) ldA_krow(a[i], A, wm * 64 + i * 16, ks * 16);
        else    ldA_rowk(a[i], A, wm * 64 + i * 16, ks * 16);
    }
    if (BM == 1) {
        ldB_krow(bb[0], B, wn * 32 + 0,  ks * 16);
        ldB_krow(bb[1], B, wn * 32 + 16, ks * 16);
    } else {
        ldB_rowk(bb[0], B, wn * 32 + 0,  ks * 16);
        ldB_rowk(bb[1], B, wn * 32 + 16, ks * 16);
    }
}

// ---------------- chunk compute (128x128x64), 64x32 tile, reg double-buffered ----------------
template <bool AT, int BM>
__device__ __forceinline__ void comp(uint32_t A, uint32_t B,
                                     float acc[4][4][4], int wm, int wn) {
    uint32_t a[2][4][4], bb[2][2][4];
    loadstep<AT, BM>(A, B, 0, a[0], bb[0], wm, wn);
#pragma unroll
    for (int ks = 0; ks < 4; ks++) {
        const int cur = ks & 1, nxt = cur ^ 1;
        if (ks < 3) loadstep<AT, BM>(A, B, ks + 1, a[nxt], bb[nxt], wm, wn);
#pragma unroll
        for (int i = 0; i < 4; i++)
#pragma unroll
            for (int j = 0; j < 4; j++)
                mma_bf16(acc[i][j], a[cur][i], &bb[cur][j >> 1][(j & 1) * 2]);
    }
}

// ---------------- persistent warp-specialized GEMM core (TPC tiles per CTA) ----------------
template <bool AT, int BM, class Epi>
__device__ __forceinline__ void gemm_ws_multi(char* smemp,
                                              const __nv_bfloat16* Ag, size_t lda, size_t astep,
                                              const __nv_bfloat16* Bg, size_t ldb, size_t bstep,
                                              int NC, int TPC, Epi& epi) {
    constexpr uint32_t ASZ = AT ? KROW_B : ROWK_B;
    constexpr uint32_t BSZ = (BM == 1) ? KROW_B : ROWK_B;
    const uint32_t sbase = (uint32_t)__cvta_generic_to_shared(smemp);
    float* red = (float*)(smemp + 128);
    const uint32_t sA0 = sbase + SM_BUF0, sB0 = sA0 + NST * ASZ;
    const int tid = threadIdx.x, wid = tid >> 5, lane = tid & 31;

    if (tid == 0) {
#pragma unroll
        for (int s = 0; s < NST; s++) {
            mbar_init(sbase + 8 * s, 128);       // full: 128 producer threads (noinc)
            mbar_init(sbase + 64 + 8 * s, 8);    // empty: 8 consumer warps
        }
    }
    __syncthreads();

    if (wid >= 8) {
        // ---- producer: 4 warps, 128 threads; streams across tile boundaries ----
        const int pt = tid & 127;
        int s = 0, ph = 1;
        for (int t = 0; t < TPC; t++) {
            const __nv_bfloat16* At = Ag + (size_t)t * astep;
            const __nv_bfloat16* Bt = Bg + (size_t)t * bstep;
            for (int c = 0; c < NC; c++) {
                mbar_wait(sbase + 64 + 8 * s, ph);
                const __nv_bfloat16* ga = At + (AT ? (size_t)(c * 64) * lda : (size_t)(c * 64));
                const __nv_bfloat16* gb = Bt + ((BM == 1) ? (size_t)(c * 64) * ldb : (size_t)(c * 64));
                if (AT) pstage_krow(sA0 + s * ASZ, ga, lda, pt);
                else    pstage_rowk(sA0 + s * ASZ, ga, lda, pt);
                if (BM == 1) pstage_krow(sB0 + s * BSZ, gb, ldb, pt);
                else         pstage_rowk(sB0 + s * BSZ, gb, ldb, pt);
                asm volatile("cp.async.mbarrier.arrive.noinc.shared.b64 [%0];"
                             :: "r"(sbase + 8 * s) : "memory");
                if (++s == NST) { s = 0; ph ^= 1; }
            }
        }
    } else {
        // ---- consumer: 8 warps; per-tile epilogue overlaps producer prefetch ----
        const int wm = wid >> 2, wn = wid & 3;
        int s = 0, ph = 0;
        for (int t = 0; t < TPC; t++) {
            float acc[4][4][4] = {};
            for (int c = 0; c < NC; c++) {
                mbar_wait(sbase + 8 * s, ph);
                comp<AT, BM>(sA0 + s * ASZ, sB0 + s * BSZ, acc, wm, wn);
                __syncwarp();
                if (lane == 0)
                    asm volatile("mbarrier.arrive.shared.b64 _, [%0];"
                                 :: "r"(sbase + 64 + 8 * s) : "memory");
                if (++s == NST) { s = 0; ph ^= 1; }
            }
            epi(acc, t, wm, wn, lane);
        }
        epi.finalize(red, tid);
    }
}

// ---------------- epilogue functors ----------------
struct EpiQKV {
    const float* bias; __nv_bfloat16* out; int mbase, n0;
    __device__ void operator()(float acc[4][4][4], int t, int wm, int wn, int lane) const {
        const int m0 = mbase + t * 128;
        const float mult = (m0 < 512) ? SCALE : 1.0f;
#pragma unroll
        for (int i = 0; i < 4; i++) {
            const int m = m0 + wm * 64 + i * 16 + (lane >> 2);
            const float b0 = bias[m], b1 = bias[m + 8];
#pragma unroll
            for (int j = 0; j < 4; j++) {
                const int n = n0 + wn * 32 + j * 8 + 2 * (lane & 3);
                *(uint32_t*)(out + (size_t)m * NSP + n) =
                    pack_bf16((acc[i][j][0] + b0) * mult, (acc[i][j][1] + b0) * mult);
                *(uint32_t*)(out + (size_t)(m + 8) * NSP + n) =
                    pack_bf16((acc[i][j][2] + b1) * mult, (acc[i][j][3] + b1) * mult);
            }
        }
    }
    __device__ void finalize(float*, int) const {}
};
// S epilogue: write unnormalized exp(S) bf16; accumulate row sums across tiles.
struct EpiS {
    __nv_bfloat16* Pp; float* gpart; int i0, jbase;
    float rsum[8];
    __device__ void operator()(float acc[4][4][4], int t, int wm, int wn, int lane) {
        const int n0 = jbase + t * 128;
#pragma unroll
        for (int i = 0; i < 4; i++) {
            const int m = i0 + wm * 64 + i * 16 + (lane >> 2);
#pragma unroll
            for (int j = 0; j < 4; j++) {
                const int n = n0 + wn * 32 + j * 8 + 2 * (lane & 3);
                const float e0 = __expf(acc[i][j][0]);
                const float e1 = __expf(acc[i][j][1]);
                const float e2 = __expf(acc[i][j][2]);
                const float e3 = __expf(acc[i][j][3]);
                *(uint32_t*)(Pp + (size_t)m * NSP + n) = pack_bf16(e0, e1);
                *(uint32_t*)(Pp + (size_t)(m + 8) * NSP + n) = pack_bf16(e2, e3);
                rsum[i * 2]     += e0 + e1;
                rsum[i * 2 + 1] += e2 + e3;
            }
        }
    }
    __device__ void finalize(float* red, int tid) {
        const int lane = tid & 31, wid = tid >> 5;
        const int wm = wid >> 2, wn = wid & 3;
#pragma unroll
        for (int k = 0; k < 8; k++) {
            rsum[k] += __shfl_xor_sync(~0u, rsum[k], 1);
            rsum[k] += __shfl_xor_sync(~0u, rsum[k], 2);
        }
        if ((lane & 3) == 0) {
#pragma unroll
            for (int i = 0; i < 4; i++) {
                const int r0 = wm * 64 + i * 16 + (lane >> 2);
                red[wn * 128 + r0]     = rsum[i * 2];
                red[wn * 128 + r0 + 8] = rsum[i * 2 + 1];
            }
        }
        asm volatile("bar.sync 1, 256;" ::: "memory");
        if (tid < 128)
            gpart[tid] = (red[tid] + red[128 + tid]) + (red[256 + tid] + red[384 + tid]);
    }
};
struct EpiAV {
    __nv_bfloat16* out; const float* rinv; int m0, n0;
    __device__ void operator()(float acc[4][4][4], int t, int wm, int wn, int lane) const {
#pragma unroll
        for (int i = 0; i < 4; i++) {
            const int m = m0 + wm * 64 + i * 16 + (lane >> 2);
#pragma unroll
            for (int j = 0; j < 4; j++) {
                const int nl = wn * 32 + j * 8 + 2 * (lane & 3);
                const float2 r2 = *(const float2*)(rinv + nl);
                const int n = n0 + nl;
                *(uint32_t*)(out + (size_t)m * NSP + n) =
                    pack_bf16(acc[i][j][0] * r2.x, acc[i][j][1] * r2.y);
                *(uint32_t*)(out + (size_t)(m + 8) * NSP + n) =
                    pack_bf16(acc[i][j][2] * r2.x, acc[i][j][3] * r2.y);
            }
        }
    }
    __device__ void finalize(float*, int) const {}
};
struct EpiOut {
    const float* bias; const float* x; float* y; int m0, nbase; size_t boff;
    __device__ void operator()(float acc[4][4][4], int t, int wm, int wn, int lane) const {
        const int n0 = nbase + t * 128;
#pragma unroll
        for (int i = 0; i < 4; i++) {
            const int m = m0 + wm * 64 + i * 16 + (lane >> 2);
            const float b0 = bias[m], b1 = bias[m + 8];
#pragma unroll
            for (int j = 0; j < 4; j++) {
                const int n = n0 + wn * 32 + j * 8 + 2 * (lane & 3);
                const size_t o0 = boff + (size_t)m * NSP + n;
                const size_t o1 = boff + (size_t)(m + 8) * NSP + n;
                float2 x0 = *(const float2*)(x + o0);
                float2 x1 = *(const float2*)(x + o1);
                *(float2*)(y + o0) =
                    make_float2(acc[i][j][0] + b0 + x0.x, acc[i][j][1] + b0 + x0.y);
                *(float2*)(y + o1) =
                    make_float2(acc[i][j][2] + b1 + x1.x, acc[i][j][3] + b1 + x1.y);
            }
        }
    }
    __device__ void finalize(float*, int) const {}
};

// ---------------- weight convert ----------------
__global__ void convert_kernel(const float* __restrict__ src,
                               __nv_bfloat16* __restrict__ dst, int n4) {
    const int i = blockIdx.x * 256 + threadIdx.x;
    if (i < n4) {
        float4 v = ((const float4*)src)[i];
        uint2 o;
        o.x = pack_bf16(v.x, v.y);
        o.y = pack_bf16(v.z, v.w);
        ((uint2*)dst)[i] = o;
    }
}

// ---------------- GroupNorm -> bf16 h [b][c][n] ----------------
__global__ void gn_kernel(const float* __restrict__ x,
                          const float* __restrict__ gamma,
                          const float* __restrict__ beta) {
    const int b = blockIdx.x >> 5;
    const int g = blockIdx.x & 31;
    const size_t base = ((size_t)b * CH + (size_t)g * 16) * NSP;
    const float4* x4 = (const float4*)(x + base);
    uint2* h4 = (uint2*)(g_hb + base);
    const int tid = threadIdx.x;
    const int NV = 16 * NSP / 4;

    float s = 0.f, ss = 0.f;
    for (int i = tid; i < NV; i += 512) {
        float4 v = x4[i];
        s  += v.x + v.y + v.z + v.w;
        ss += v.x * v.x + v.y * v.y + v.z * v.z + v.w * v.w;
    }
    __shared__ float rs[512], rq[512];
    rs[tid] = s; rq[tid] = ss;
    __syncthreads();
    for (int o = 256; o > 0; o >>= 1) {
        if (tid < o) { rs[tid] += rs[tid + o]; rq[tid] += rq[tid + o]; }
        __syncthreads();
    }
    const float inv_n = 1.f / (float)(16 * NSP);
    const float mean  = rs[0] * inv_n;
    const float var   = rq[0] * inv_n - mean * mean;
    const float rstd  = rsqrtf(var + 1e-5f);

    for (int i = tid; i < NV; i += 512) {
        const int c = g * 16 + (i >> 10);
        const float ga = gamma[c] * rstd;
        const float be = beta[c] - mean * ga;
        float4 v = x4[i];
        uint2 o;
        o.x = pack_bf16(v.x * ga + be, v.y * ga + be);
        o.y = pack_bf16(v.z * ga + be, v.w * ga + be);
        h4[i] = o;
    }
}

// ---------------- rowsum: rinv[b][i] = 1 / sum_g partial[b][g][i] ----------------
__global__ void rowsum_kernel() {
    const int idx = blockIdx.x * 256 + threadIdx.x;   // 32768 total
    const int b = idx >> 12, i = idx & 4095;
    float s = 0.f;
#pragma unroll
    for (int g = 0; g < 8; g++)
        s += g_partial[((size_t)b * 8 + g) * NSP + i];
    g_rinv[(size_t)b * NSP + i] = 1.0f / s;
}

// ---------------- QKV: persistent over 2 m-tiles ----------------
__global__ __launch_bounds__(384, 1) void qkv_kernel(const float* __restrict__ bias) {
    const int b = blockIdx.z;
    const int mbase = blockIdx.y * 256, n0 = blockIdx.x * 128;
    extern __shared__ __align__(16) char smem[];
    EpiQKV epi{bias, g_qkvb + (size_t)b * 3 * CH * NSP, mbase, n0};
    gemm_ws_multi<false, 1>(smem,
        g_wqkvb + (size_t)mbase * CH, CH, (size_t)128 * CH,
        g_hb + (size_t)b * CH * NSP + n0, NSP, 0,
        8, 2, epi);
}

// ---------------- S: persistent over 4 j-tiles, fused exp + row-sum partials ----------------
__global__ __launch_bounds__(384, 1) void s_kernel() {
    const int b = blockIdx.z;
    const int i0 = blockIdx.y * 128, jbase = blockIdx.x * 512;
    extern __shared__ __align__(16) char smem[];
    EpiS epi{g_pb + (size_t)b * NSP * NSP,
             g_partial + ((size_t)b * 8 + blockIdx.x) * NSP + i0,
             i0, jbase};
    gemm_ws_multi<true, 1>(smem,
        g_qkvb + (size_t)b * 3 * CH * NSP + i0, NSP, 0,
        g_qkvb + ((size_t)b * 3 + 1) * CH * NSP + jbase, NSP, 128,
        8, 4, epi);
}

// ---------------- AV: out2[c,i] = (sum_j V[c,j] * e[i,j]) * rinv[i] ----------------
__global__ __launch_bounds__(384, 1) void av_kernel() {
    const int b = blockIdx.z;
    const int m0 = blockIdx.x * 128, n0 = blockIdx.y * 128;   // m=c, n=i
    extern __shared__ __align__(16) char smem[];
    EpiAV epi{g_out2b + (size_t)b * CH * NSP, g_rinv + (size_t)b * NSP + n0, m0, n0};
    gemm_ws_multi<false, 0>(smem,
        g_qkvb + ((size_t)b * 3 + 2) * CH * NSP + (size_t)m0 * NSP, NSP, 0,
        g_pb + (size_t)b * NSP * NSP + (size_t)n0 * NSP, NSP, 0,
        64, 1, epi);
}

// ---------------- out: persistent over 2 n-tiles ----------------
__global__ __launch_bounds__(384, 1) void out_kernel(const float* __restrict__ bias,
                                                     const float* __restrict__ x,
                                                     float* __restrict__ y) {
    const int b = blockIdx.z;
    const int m0 = blockIdx.y * 128, nbase = blockIdx.x * 256;
    extern __shared__ __align__(16) char smem[];
    EpiOut epi{bias, x, y, m0, nbase, (size_t)b * CH * NSP};
    gemm_ws_multi<false, 1>(smem,
        g_woutb + (size_t)m0 * CH, CH, 0,
        g_out2b + (size_t)b * CH * NSP + nbase, NSP, 128,
        8, 2, epi);
}

// ---------------- launch ----------------
extern "C" void kernel_launch(void* const* d_in, const int* in_sizes, int n_in,
                              void* d_out, int out_size) {
    const float* x     = (const float*)d_in[0];
    const float* gamma = (const float*)d_in[1];
    const float* beta  = (const float*)d_in[2];
    const float* w_qkv = (const float*)d_in[3];
    const float* b_qkv = (const float*)d_in[4];
    const float* w_out = (const float*)d_in[5];
    const float* b_out = (const float*)d_in[6];
    float* y = (float*)d_out;

    __nv_bfloat16* wq; cudaGetSymbolAddress((void**)&wq, g_wqkvb);
    __nv_bfloat16* wo; cudaGetSymbolAddress((void**)&wo, g_woutb);

    const int SM_MIX = SM_BUF0 + NST * (ROWK_B + KROW_B);  // 181376
    const int SM_KK  = SM_BUF0 + NST * (2 * KROW_B);       // 176256
    const int SM_RR  = SM_BUF0 + NST * (2 * ROWK_B);       // 186496
    cudaFuncSetAttribute(qkv_kernel, cudaFuncAttributeMaxDynamicSharedMemorySize, SM_MIX);
    cudaFuncSetAttribute(s_kernel,   cudaFuncAttributeMaxDynamicSharedMemorySize, SM_KK);
    cudaFuncSetAttribute(av_kernel,  cudaFuncAttributeMaxDynamicSharedMemorySize, SM_RR);
    cudaFuncSetAttribute(out_kernel, cudaFuncAttributeMaxDynamicSharedMemorySize, SM_MIX);

    convert_kernel<<<768, 256>>>(w_qkv, wq, 3 * CH * CH / 4);
    convert_kernel<<<256, 256>>>(w_out, wo, CH * CH / 4);
    gn_kernel<<<BATCH * 32, 512>>>(x, gamma, beta);
    qkv_kernel<<<dim3(NSP / 128, 6, BATCH), 384, SM_MIX>>>(b_qkv);          // 2 m-tiles/CTA
    s_kernel<<<dim3(NSP / 512, NSP / 128, BATCH), 384, SM_KK>>>();          // 4 j-tiles/CTA
    rowsum_kernel<<<BATCH * NSP / 256, 256>>>();
    av_kernel<<<dim3(CH / 128, NSP / 128, BATCH), 384, SM_RR>>>();
    out_kernel<<<dim3(NSP / 256, CH / 128, BATCH), 384, SM_MIX>>>(b_out, x, y);
}

// round 17
// speedup vs baseline: 1.1147x; 1.0105x over previous
#include <cuda_runtime.h>
#include <cuda_fp16.h>
#include <math.h>
#include <stdint.h>

#define BATCH 8
#define CH    512
#define NSP   4096
#define SCALE 0.044194173824159216f   // 1/sqrt(512)

#define ROWK_B 18432u   // 128 rows x 64 halves, stride 144B
#define KROW_B 17408u   // 64 rows x 128 halves, stride 272B
#define NST 5
#define SM_BUF0 2176u   // 128 mbar + 2048 reduce scratch

// ---------------- scratch (device globals, all fp16) ----------------
__device__ __half g_hb   [(size_t)BATCH * CH * NSP];       //  [b][c][n]
__device__ __half g_qkvb [(size_t)BATCH * 3 * CH * NSP];   //  [b][o][n]
__device__ __half g_pb   [(size_t)BATCH * NSP * NSP];      //  unnormalized exp(S)
__device__ __half g_out2b[(size_t)BATCH * CH * NSP];       //  [b][c][n]
__device__ float  g_partial[(size_t)BATCH * 8 * NSP];      //  row-sum partials
__device__ float  g_rinv [(size_t)BATCH * NSP];            //  1/rowsum
__device__ __half g_wqkvb[(size_t)3 * CH * CH];
__device__ __half g_woutb[(size_t)CH * CH];

// ---------------- helpers ----------------
__device__ __forceinline__ uint32_t pack_f16(float x, float y) {
    __half2 h = __floats2half2_rn(x, y);
    return *reinterpret_cast<uint32_t*>(&h);
}
__device__ __forceinline__ float2 unpack_f16(uint32_t u) {
    return __half22float2(*reinterpret_cast<__half2*>(&u));
}
__device__ __forceinline__ void cp16(uint32_t s, const void* g) {
    asm volatile("cp.async.cg.shared.global [%0], [%1], 16;\n" :: "r"(s), "l"(g));
}
__device__ __forceinline__ void mbar_init(uint32_t a, uint32_t cnt) {
    asm volatile("mbarrier.init.shared.b64 [%0], %1;" :: "r"(a), "r"(cnt) : "memory");
}
__device__ __forceinline__ void mbar_wait(uint32_t a, uint32_t par) {
    uint32_t done;
    asm volatile("{\n\t.reg .pred p;\n\t"
        "mbarrier.try_wait.parity.acquire.cta.shared::cta.b64 p, [%1], %2;\n\t"
        "selp.b32 %0, 1, 0, p;\n\t}" : "=r"(done) : "r"(a), "r"(par) : "memory");
    while (!done) {
        asm volatile("{\n\t.reg .pred p;\n\t"
            "mbarrier.try_wait.parity.acquire.cta.shared::cta.b64 p, [%1], %2, 0x989680;\n\t"
            "selp.b32 %0, 1, 0, p;\n\t}" : "=r"(done) : "r"(a), "r"(par) : "memory");
    }
}
// fp32-accumulate (AV)
__device__ __forceinline__ void mma_f32(float* d, const uint32_t* a, const uint32_t* b) {
    asm volatile(
        "mma.sync.aligned.m16n8k16.row.col.f32.f16.f16.f32 "
        "{%0,%1,%2,%3}, {%4,%5,%6,%7}, {%8,%9}, {%0,%1,%2,%3};\n"
        : "+f"(d[0]), "+f"(d[1]), "+f"(d[2]), "+f"(d[3])
        : "r"(a[0]), "r"(a[1]), "r"(a[2]), "r"(a[3]), "r"(b[0]), "r"(b[1]));
}
// fp16-accumulate (qkv, S, out)
__device__ __forceinline__ void mma_f16(uint32_t* d, const uint32_t* a, const uint32_t* b) {
    asm volatile(
        "mma.sync.aligned.m16n8k16.row.col.f16.f16.f16.f16 "
        "{%0,%1}, {%2,%3,%4,%5}, {%6,%7}, {%0,%1};\n"
        : "+r"(d[0]), "+r"(d[1])
        : "r"(a[0]), "r"(a[1]), "r"(a[2]), "r"(a[3]), "r"(b[0]), "r"(b[1]));
}
__device__ __forceinline__ void ldm_x4(uint32_t* r, uint32_t addr) {
    asm volatile("ldmatrix.sync.aligned.m8n8.x4.shared.b16 {%0,%1,%2,%3}, [%4];\n"
                 : "=r"(r[0]), "=r"(r[1]), "=r"(r[2]), "=r"(r[3]) : "r"(addr));
}
__device__ __forceinline__ void ldm_x4t(uint32_t* r, uint32_t addr) {
    asm volatile("ldmatrix.sync.aligned.m8n8.x4.trans.shared.b16 {%0,%1,%2,%3}, [%4];\n"
                 : "=r"(r[0]), "=r"(r[1]), "=r"(r[2]), "=r"(r[3]) : "r"(addr));
}

// ---------------- producer staging (128 threads) ----------------
__device__ __forceinline__ void pstage_rowk(uint32_t sb, const __half* g,
                                            size_t ld, int pt) {
#pragma unroll
    for (int p = 0; p < 8; p++) {
        const int idx = pt + p * 128;
        const int row = idx >> 3, c = idx & 7;
        cp16(sb + row * 144 + c * 16, g + (size_t)row * ld + c * 8);
    }
}
__device__ __forceinline__ void pstage_krow(uint32_t sb, const __half* g,
                                            size_t ld, int pt) {
#pragma unroll
    for (int p = 0; p < 8; p++) {
        const int idx = pt + p * 128;
        const int row = idx >> 4, c = idx & 15;
        cp16(sb + row * 272 + c * 16, g + (size_t)row * ld + c * 8);
    }
}

// ---------------- ldmatrix fragment loaders ----------------
__device__ __forceinline__ void ldA_rowk(uint32_t* a, uint32_t base, int M0, int kk) {
    const int l = threadIdx.x & 31;
    const uint32_t addr = base + (uint32_t)(M0 + (l & 15)) * 144
                               + (uint32_t)(kk + ((l >> 4) << 3)) * 2;
    ldm_x4(a, addr);
}
__device__ __forceinline__ void ldB_rowk(uint32_t* b, uint32_t base, int N0, int kk) {
    const int l = threadIdx.x & 31;
    const uint32_t addr = base + (uint32_t)(N0 + ((l >> 4) << 3) + (l & 7)) * 144
                               + (uint32_t)(kk + (((l >> 3) & 1) << 3)) * 2;
    ldm_x4(b, addr);
}
__device__ __forceinline__ void ldA_krow(uint32_t* a, uint32_t base, int M0, int kk) {
    const int l = threadIdx.x & 31;
    const int gq = l >> 3, lr = l & 7;
    const uint32_t addr = base + (uint32_t)(kk + lr + ((gq & 2) ? 8 : 0)) * 272
                               + (uint32_t)(M0 + ((gq & 1) ? 8 : 0)) * 2;
    ldm_x4t(a, addr);
}
__device__ __forceinline__ void ldB_krow(uint32_t* b, uint32_t base, int N0, int kk) {
    const int l = threadIdx.x & 31;
    const int gq = l >> 3, lr = l & 7;
    const uint32_t addr = base + (uint32_t)(kk + lr + ((gq & 1) ? 8 : 0)) * 272
                               + (uint32_t)(N0 + ((gq & 2) ? 8 : 0)) * 2;
    ldm_x4t(b, addr);
}

// ---------------- one k16-step fragment load ----------------
template <bool AT, int BM>
__device__ __forceinline__ void loadstep(uint32_t A, uint32_t B, int ks,
                                         uint32_t a[4][4], uint32_t bb[2][4],
                                         int wm, int wn) {
#pragma unroll
    for (int i = 0; i < 4; i++) {
        if (AT) ldA_krow(a[i], A, wm * 64 + i * 16, ks * 16);
        else    ldA_rowk(a[i], A, wm * 64 + i * 16, ks * 16);
    }
    if (BM == 1) {
        ldB_krow(bb[0], B, wn * 32 + 0,  ks * 16);
        ldB_krow(bb[1], B, wn * 32 + 16, ks * 16);
    } else {
        ldB_rowk(bb[0], B, wn * 32 + 0,  ks * 16);
        ldB_rowk(bb[1], B, wn * 32 + 16, ks * 16);
    }
}

// ---------------- chunk compute, fp32 acc ----------------
template <bool AT, int BM>
__device__ __forceinline__ void comp32(uint32_t A, uint32_t B,
                                       float acc[4][4][4], int wm, int wn) {
    uint32_t a[2][4][4], bb[2][2][4];
    loadstep<AT, BM>(A, B, 0, a[0], bb[0], wm, wn);
#pragma unroll
    for (int ks = 0; ks < 4; ks++) {
        const int cur = ks & 1, nxt = cur ^ 1;
        if (ks < 3) loadstep<AT, BM>(A, B, ks + 1, a[nxt], bb[nxt], wm, wn);
#pragma unroll
        for (int i = 0; i < 4; i++)
#pragma unroll
            for (int j = 0; j < 4; j++)
                mma_f32(acc[i][j], a[cur][i], &bb[cur][j >> 1][(j & 1) * 2]);
    }
}
// ---------------- chunk compute, fp16 acc ----------------
template <bool AT, int BM>
__device__ __forceinline__ void comp16(uint32_t A, uint32_t B,
                                       uint32_t acc[4][4][2], int wm, int wn) {
    uint32_t a[2][4][4], bb[2][2][4];
    loadstep<AT, BM>(A, B, 0, a[0], bb[0], wm, wn);
#pragma unroll
    for (int ks = 0; ks < 4; ks++) {
        const int cur = ks & 1, nxt = cur ^ 1;
        if (ks < 3) loadstep<AT, BM>(A, B, ks + 1, a[nxt], bb[nxt], wm, wn);
#pragma unroll
        for (int i = 0; i < 4; i++)
#pragma unroll
            for (int j = 0; j < 4; j++)
                mma_f16(acc[i][j], a[cur][i], &bb[cur][j >> 1][(j & 1) * 2]);
    }
}

// ---------------- persistent warp-specialized GEMM core ----------------
// HACC=1: fp16 accumulators (epi gets uint32 acc[4][4][2]); HACC=0: fp32.
template <bool AT, int BM, int HACC, class Epi>
__device__ __forceinline__ void gemm_ws_multi(char* smemp,
                                              const __half* Ag, size_t lda, size_t astep,
                                              const __half* Bg, size_t ldb, size_t bstep,
                                              int NC, int TPC, Epi& epi) {
    constexpr uint32_t ASZ = AT ? KROW_B : ROWK_B;
    constexpr uint32_t BSZ = (BM == 1) ? KROW_B : ROWK_B;
    const uint32_t sbase = (uint32_t)__cvta_generic_to_shared(smemp);
    float* red = (float*)(smemp + 128);
    const uint32_t sA0 = sbase + SM_BUF0, sB0 = sA0 + NST * ASZ;
    const int tid = threadIdx.x, wid = tid >> 5, lane = tid & 31;

    if (tid == 0) {
#pragma unroll
        for (int s = 0; s < NST; s++) {
            mbar_init(sbase + 8 * s, 128);
            mbar_init(sbase + 64 + 8 * s, 8);
        }
    }
    __syncthreads();

    if (wid >= 8) {
        const int pt = tid & 127;
        int s = 0, ph = 1;
        for (int t = 0; t < TPC; t++) {
            const __half* At = Ag + (size_t)t * astep;
            const __half* Bt = Bg + (size_t)t * bstep;
            for (int c = 0; c < NC; c++) {
                mbar_wait(sbase + 64 + 8 * s, ph);
                const __half* ga = At + (AT ? (size_t)(c * 64) * lda : (size_t)(c * 64));
                const __half* gb = Bt + ((BM == 1) ? (size_t)(c * 64) * ldb : (size_t)(c * 64));
                if (AT) pstage_krow(sA0 + s * ASZ, ga, lda, pt);
                else    pstage_rowk(sA0 + s * ASZ, ga, lda, pt);
                if (BM == 1) pstage_krow(sB0 + s * BSZ, gb, ldb, pt);
                else         pstage_rowk(sB0 + s * BSZ, gb, ldb, pt);
                asm volatile("cp.async.mbarrier.arrive.noinc.shared.b64 [%0];"
                             :: "r"(sbase + 8 * s) : "memory");
                if (++s == NST) { s = 0; ph ^= 1; }
            }
        }
    } else {
        const int wm = wid >> 2, wn = wid & 3;
        int s = 0, ph = 0;
        for (int t = 0; t < TPC; t++) {
            if (HACC) {
                uint32_t acc[4][4][2] = {};
                for (int c = 0; c < NC; c++) {
                    mbar_wait(sbase + 8 * s, ph);
                    comp16<AT, BM>(sA0 + s * ASZ, sB0 + s * BSZ, acc, wm, wn);
                    __syncwarp();
                    if (lane == 0)
                        asm volatile("mbarrier.arrive.shared.b64 _, [%0];"
                                     :: "r"(sbase + 64 + 8 * s) : "memory");
                    if (++s == NST) { s = 0; ph ^= 1; }
                }
                epi.store16(acc, t, wm, wn, lane);
            } else {
                float acc[4][4][4] = {};
                for (int c = 0; c < NC; c++) {
                    mbar_wait(sbase + 8 * s, ph);
                    comp32<AT, BM>(sA0 + s * ASZ, sB0 + s * BSZ, acc, wm, wn);
                    __syncwarp();
                    if (lane == 0)
                        asm volatile("mbarrier.arrive.shared.b64 _, [%0];"
                                     :: "r"(sbase + 64 + 8 * s) : "memory");
                    if (++s == NST) { s = 0; ph ^= 1; }
                }
                epi.store32(acc, t, wm, wn, lane);
            }
        }
        epi.finalize(red, tid);
    }
}

// ---------------- epilogue functors ----------------
struct EpiQKV {
    const float* bias; __half* out; int mbase, n0;
    __device__ void store16(uint32_t acc[4][4][2], int t, int wm, int wn, int lane) const {
        const int m0 = mbase + t * 128;
        const float mult = (m0 < 512) ? SCALE : 1.0f;
#pragma unroll
        for (int i = 0; i < 4; i++) {
            const int m = m0 + wm * 64 + i * 16 + (lane >> 2);
            const float b0 = bias[m], b1 = bias[m + 8];
#pragma unroll
            for (int j = 0; j < 4; j++) {
                const int n = n0 + wn * 32 + j * 8 + 2 * (lane & 3);
                float2 f0 = unpack_f16(acc[i][j][0]);
                float2 f1 = unpack_f16(acc[i][j][1]);
                *(uint32_t*)(out + (size_t)m * NSP + n) =
                    pack_f16((f0.x + b0) * mult, (f0.y + b0) * mult);
                *(uint32_t*)(out + (size_t)(m + 8) * NSP + n) =
                    pack_f16((f1.x + b1) * mult, (f1.y + b1) * mult);
            }
        }
    }
    __device__ void store32(float[4][4][4], int, int, int, int) const {}
    __device__ void finalize(float*, int) const {}
};
struct EpiS {
    __half* Pp; float* gpart; int i0, jbase;
    float rsum[8];
    __device__ void store16(uint32_t acc[4][4][2], int t, int wm, int wn, int lane) {
        const int n0 = jbase + t * 128;
#pragma unroll
        for (int i = 0; i < 4; i++) {
            const int m = i0 + wm * 64 + i * 16 + (lane >> 2);
#pragma unroll
            for (int j = 0; j < 4; j++) {
                const int n = n0 + wn * 32 + j * 8 + 2 * (lane & 3);
                float2 f0 = unpack_f16(acc[i][j][0]);
                float2 f1 = unpack_f16(acc[i][j][1]);
                const float e0 = __expf(f0.x), e1 = __expf(f0.y);
                const float e2 = __expf(f1.x), e3 = __expf(f1.y);
                *(uint32_t*)(Pp + (size_t)m * NSP + n) = pack_f16(e0, e1);
                *(uint32_t*)(Pp + (size_t)(m + 8) * NSP + n) = pack_f16(e2, e3);
                rsum[i * 2]     += e0 + e1;
                rsum[i * 2 + 1] += e2 + e3;
            }
        }
    }
    __device__ void store32(float[4][4][4], int, int, int, int) const {}
    __device__ void finalize(float* red, int tid) {
        const int lane = tid & 31, wid = tid >> 5;
        const int wm = wid >> 2, wn = wid & 3;
#pragma unroll
        for (int k = 0; k < 8; k++) {
            rsum[k] += __shfl_xor_sync(~0u, rsum[k], 1);
            rsum[k] += __shfl_xor_sync(~0u, rsum[k], 2);
        }
        if ((lane & 3) == 0) {
#pragma unroll
            for (int i = 0; i < 4; i++) {
                const int r0 = wm * 64 + i * 16 + (lane >> 2);
                red[wn * 128 + r0]     = rsum[i * 2];
                red[wn * 128 + r0 + 8] = rsum[i * 2 + 1];
            }
        }
        asm volatile("bar.sync 1, 256;" ::: "memory");
        if (tid < 128)
            gpart[tid] = (red[tid] + red[128 + tid]) + (red[256 + tid] + red[384 + tid]);
    }
};
struct EpiAV {
    __half* out; const float* rinv; int m0, n0;
    __device__ void store32(float acc[4][4][4], int t, int wm, int wn, int lane) const {
#pragma unroll
        for (int i = 0; i < 4; i++) {
            const int m = m0 + wm * 64 + i * 16 + (lane >> 2);
#pragma unroll
            for (int j = 0; j < 4; j++) {
                const int nl = wn * 32 + j * 8 + 2 * (lane & 3);
                const float2 r2 = *(const float2*)(rinv + nl);
                const int n = n0 + nl;
                *(uint32_t*)(out + (size_t)m * NSP + n) =
                    pack_f16(acc[i][j][0] * r2.x, acc[i][j][1] * r2.y);
                *(uint32_t*)(out + (size_t)(m + 8) * NSP + n) =
                    pack_f16(acc[i][j][2] * r2.x, acc[i][j][3] * r2.y);
            }
        }
    }
    __device__ void store16(uint32_t[4][4][2], int, int, int, int) const {}
    __device__ void finalize(float*, int) const {}
};
struct EpiOut {
    const float* bias; const float* x; float* y; int m0, nbase; size_t boff;
    __device__ void store16(uint32_t acc[4][4][2], int t, int wm, int wn, int lane) const {
        const int n0 = nbase + t * 128;
#pragma unroll
        for (int i = 0; i < 4; i++) {
            const int m = m0 + wm * 64 + i * 16 + (lane >> 2);
            const float b0 = bias[m], b1 = bias[m + 8];
#pragma unroll
            for (int j = 0; j < 4; j++) {
                const int n = n0 + wn * 32 + j * 8 + 2 * (lane & 3);
                const size_t o0 = boff + (size_t)m * NSP + n;
                const size_t o1 = boff + (size_t)(m + 8) * NSP + n;
                float2 x0 = *(const float2*)(x + o0);
                float2 x1 = *(const float2*)(x + o1);
                float2 f0 = unpack_f16(acc[i][j][0]);
                float2 f1 = unpack_f16(acc[i][j][1]);
                *(float2*)(y + o0) = make_float2(f0.x + b0 + x0.x, f0.y + b0 + x0.y);
                *(float2*)(y + o1) = make_float2(f1.x + b1 + x1.x, f1.y + b1 + x1.y);
            }
        }
    }
    __device__ void store32(float[4][4][4], int, int, int, int) const {}
    __device__ void finalize(float*, int) const {}
};

// ---------------- weight convert (fp32 -> fp16) ----------------
__global__ void convert_kernel(const float* __restrict__ src,
                               __half* __restrict__ dst, int n4) {
    const int i = blockIdx.x * 256 + threadIdx.x;
    if (i < n4) {
        float4 v = ((const float4*)src)[i];
        uint2 o;
        o.x = pack_f16(v.x, v.y);
        o.y = pack_f16(v.z, v.w);
        ((uint2*)dst)[i] = o;
    }
}

// ---------------- GroupNorm -> fp16 h [b][c][n] ----------------
__global__ void gn_kernel(const float* __restrict__ x,
                          const float* __restrict__ gamma,
                          const float* __restrict__ beta) {
    const int b = blockIdx.x >> 5;
    const int g = blockIdx.x & 31;
    const size_t base = ((size_t)b * CH + (size_t)g * 16) * NSP;
    const float4* x4 = (const float4*)(x + base);
    uint2* h4 = (uint2*)(g_hb + base);
    const int tid = threadIdx.x;
    const int NV = 16 * NSP / 4;

    float s = 0.f, ss = 0.f;
    for (int i = tid; i < NV; i += 512) {
        float4 v = x4[i];
        s  += v.x + v.y + v.z + v.w;
        ss += v.x * v.x + v.y * v.y + v.z * v.z + v.w * v.w;
    }
    __shared__ float rs[512], rq[512];
    rs[tid] = s; rq[tid] = ss;
    __syncthreads();
    for (int o = 256; o > 0; o >>= 1) {
        if (tid < o) { rs[tid] += rs[tid + o]; rq[tid] += rq[tid + o]; }
        __syncthreads();
    }
    const float inv_n = 1.f / (float)(16 * NSP);
    const float mean  = rs[0] * inv_n;
    const float var   = rq[0] * inv_n - mean * mean;
    const float rstd  = rsqrtf(var + 1e-5f);

    for (int i = tid; i < NV; i += 512) {
        const int c = g * 16 + (i >> 10);
        const float ga = gamma[c] * rstd;
        const float be = beta[c] - mean * ga;
        float4 v = x4[i];
        uint2 o;
        o.x = pack_f16(v.x * ga + be, v.y * ga + be);
        o.y = pack_f16(v.z * ga + be, v.w * ga + be);
        h4[i] = o;
    }
}

// ---------------- rowsum: rinv[b][i] = 1 / sum_g partial[b][g][i] ----------------
__global__ void rowsum_kernel() {
    const int idx = blockIdx.x * 256 + threadIdx.x;
    const int b = idx >> 12, i = idx & 4095;
    float s = 0.f;
#pragma unroll
    for (int g = 0; g < 8; g++)
        s += g_partial[((size_t)b * 8 + g) * NSP + i];
    g_rinv[(size_t)b * NSP + i] = 1.0f / s;
}

// ---------------- QKV: persistent over 2 m-tiles, fp16 acc ----------------
__global__ __launch_bounds__(384, 1) void qkv_kernel(const float* __restrict__ bias) {
    const int b = blockIdx.z;
    const int mbase = blockIdx.y * 256, n0 = blockIdx.x * 128;
    extern __shared__ __align__(16) char smem[];
    EpiQKV epi{bias, g_qkvb + (size_t)b * 3 * CH * NSP, mbase, n0};
    gemm_ws_multi<false, 1, 1>(smem,
        g_wqkvb + (size_t)mbase * CH, CH, (size_t)128 * CH,
        g_hb + (size_t)b * CH * NSP + n0, NSP, 0,
        8, 2, epi);
}

// ---------------- S: persistent over 4 j-tiles, fp16 acc, fused exp + rowsums ----------------
__global__ __launch_bounds__(384, 1) void s_kernel() {
    const int b = blockIdx.z;
    const int i0 = blockIdx.y * 128, jbase = blockIdx.x * 512;
    extern __shared__ __align__(16) char smem[];
    EpiS epi{g_pb + (size_t)b * NSP * NSP,
             g_partial + ((size_t)b * 8 + blockIdx.x) * NSP + i0,
             i0, jbase};
    gemm_ws_multi<true, 1, 1>(smem,
        g_qkvb + (size_t)b * 3 * CH * NSP + i0, NSP, 0,
        g_qkvb + ((size_t)b * 3 + 1) * CH * NSP + jbase, NSP, 128,
        8, 4, epi);
}

// ---------------- AV: fp32 acc (large unnormalized sums) ----------------
__global__ __launch_bounds__(384, 1) void av_kernel() {
    const int b = blockIdx.z;
    const int m0 = blockIdx.x * 128, n0 = blockIdx.y * 128;   // m=c, n=i
    extern __shared__ __align__(16) char smem[];
    EpiAV epi{g_out2b + (size_t)b * CH * NSP, g_rinv + (size_t)b * NSP + n0, m0, n0};
    gemm_ws_multi<false, 0, 0>(smem,
        g_qkvb + ((size_t)b * 3 + 2) * CH * NSP + (size_t)m0 * NSP, NSP, 0,
        g_pb + (size_t)b * NSP * NSP + (size_t)n0 * NSP, NSP, 0,
        64, 1, epi);
}

// ---------------- out: persistent over 2 n-tiles, fp16 acc ----------------
__global__ __launch_bounds__(384, 1) void out_kernel(const float* __restrict__ bias,
                                                     const float* __restrict__ x,
                                                     float* __restrict__ y) {
    const int b = blockIdx.z;
    const int m0 = blockIdx.y * 128, nbase = blockIdx.x * 256;
    extern __shared__ __align__(16) char smem[];
    EpiOut epi{bias, x, y, m0, nbase, (size_t)b * CH * NSP};
    gemm_ws_multi<false, 1, 1>(smem,
        g_woutb + (size_t)m0 * CH, CH, 0,
        g_out2b + (size_t)b * CH * NSP + nbase, NSP, 128,
        8, 2, epi);
}

// ---------------- launch ----------------
extern "C" void kernel_launch(void* const* d_in, const int* in_sizes, int n_in,
                              void* d_out, int out_size) {
    const float* x     = (const float*)d_in[0];
    const float* gamma = (const float*)d_in[1];
    const float* beta  = (const float*)d_in[2];
    const float* w_qkv = (const float*)d_in[3];
    const float* b_qkv = (const float*)d_in[4];
    const float* w_out = (const float*)d_in[5];
    const float* b_out = (const float*)d_in[6];
    float* y = (float*)d_out;

    __half* wq; cudaGetSymbolAddress((void**)&wq, g_wqkvb);
    __half* wo; cudaGetSymbolAddress((void**)&wo, g_woutb);

    const int SM_MIX = SM_BUF0 + NST * (ROWK_B + KROW_B);  // 181376
    const int SM_KK  = SM_BUF0 + NST * (2 * KROW_B);       // 176256
    const int SM_RR  = SM_BUF0 + NST * (2 * ROWK_B);       // 186496
    cudaFuncSetAttribute(qkv_kernel, cudaFuncAttributeMaxDynamicSharedMemorySize, SM_MIX);
    cudaFuncSetAttribute(s_kernel,   cudaFuncAttributeMaxDynamicSharedMemorySize, SM_KK);
    cudaFuncSetAttribute(av_kernel,  cudaFuncAttributeMaxDynamicSharedMemorySize, SM_RR);
    cudaFuncSetAttribute(out_kernel, cudaFuncAttributeMaxDynamicSharedMemorySize, SM_MIX);

    convert_kernel<<<768, 256>>>(w_qkv, wq, 3 * CH * CH / 4);
    convert_kernel<<<256, 256>>>(w_out, wo, CH * CH / 4);
    gn_kernel<<<BATCH * 32, 512>>>(x, gamma, beta);
    qkv_kernel<<<dim3(NSP / 128, 6, BATCH), 384, SM_MIX>>>(b_qkv);
    s_kernel<<<dim3(NSP / 512, NSP / 128, BATCH), 384, SM_KK>>>();
    rowsum_kernel<<<BATCH * NSP / 256, 256>>>();
    av_kernel<<<dim3(CH / 128, NSP / 128, BATCH), 384, SM_RR>>>();
    out_kernel<<<dim3(NSP / 256, CH / 128, BATCH), 384, SM_MIX>>>(b_out, x, y);
}